// round 11
// baseline (speedup 1.0000x reference)
#include <cuda_runtime.h>
#include <cuda_bf16.h>
#include <math.h>
#include <float.h>
#include <stdint.h>

// Problem constants (fixed by dataset)
#define NN 50000
#define HH 64
#define EE 250000
#define HEADS 4
#define TOT_E (2 * EE)             // edges across both paths
#define TOT_N (2 * NN)             // segments across both paths
#define ROWS_TOT (NN * 2)          // 100000 MLP rows (N nodes x 2 paths)
#define SCAN_BLOCKS ((TOT_N + 1023) / 1024)   // 98
#define MLP_GRID  148

// ---------------- scratch (static device memory; no allocs) ----------------
__device__ float g_fr[2][3][32][2];
__device__ float g_a1n[NN * 4];
__device__ int   g_counts[TOT_N];          // zero at every kernel_launch entry (scan re-zeroes)
__device__ int   g_offsets[TOT_N + 1];
__device__ int   g_cursor[TOT_N];
__device__ unsigned long long g_desc[SCAN_BLOCKS];  // decoupled-lookback descriptors
__device__ unsigned int g_bar;
__device__ __align__(8) int2 g_einst[TOT_E];  // CSR-sorted (n1,n2) per edge (n0 = segment)
__device__ float g_z[(size_t)NN * 512];       // fp32 rows: row (2n+m) x 256
__device__ __align__(16) __nv_bfloat16 g_fw1b[256 * 256];
__device__ __align__(16) __nv_bfloat16 g_fw2b[128 * 256];
__device__ float g_w[2];

// ---------------- helpers ----------------
__device__ __forceinline__ float celu3f(float x) {
    return x > 0.f ? x : 3.f * (__expf(x * (1.f / 3.f)) - 1.f);
}
// gate(x) = celu3( celu3(x) * sigmoid(x) ) with sigmoid derived from exp(x/3):
// sigmoid(x) = e^x/(e^x+1), e^x = (e^{x/3})^3  -> 3 MUFU instead of 4.
__device__ __forceinline__ float gatef(float x) {
    float e1 = __expf(x * (1.f / 3.f));
    float e3 = e1 * e1 * e1;                    // = exp(x)
    float s  = __fdividef(e3, e3 + 1.f);        // sigmoid(x)
    float c1 = x > 0.f ? x : 3.f * (e1 - 1.f);  // celu3(x)
    float se = c1 * s;
    return se > 0.f ? se : 3.f * (__expf(se * (1.f / 3.f)) - 1.f);
}
__device__ __forceinline__ float wredsum(float v) {
#pragma unroll
    for (int o = 16; o; o >>= 1) v += __shfl_xor_sync(0xffffffffu, v, o);
    return v;
}
__device__ __forceinline__ uint32_t smem_to_u32(const void* p) {
    uint32_t a;
    asm("{ .reg .u64 t; cvta.to.shared.u64 t, %1; cvt.u32.u64 %0, t; }" : "=r"(a) : "l"(p));
    return a;
}
__device__ __forceinline__ void ldsm_x4(uint32_t addr, uint32_t* r) {
    asm volatile("ldmatrix.sync.aligned.m8n8.x4.shared.b16 {%0,%1,%2,%3}, [%4];"
                 : "=r"(r[0]), "=r"(r[1]), "=r"(r[2]), "=r"(r[3]) : "r"(addr));
}
__device__ __forceinline__ void mma_bf16(float* d, const uint32_t* a, const uint32_t* b) {
    asm volatile(
        "mma.sync.aligned.m16n8k16.row.col.f32.bf16.bf16.f32 "
        "{%0,%1,%2,%3}, {%4,%5,%6,%7}, {%8,%9}, {%0,%1,%2,%3};"
        : "+f"(d[0]), "+f"(d[1]), "+f"(d[2]), "+f"(d[3])
        : "r"(a[0]), "r"(a[1]), "r"(a[2]), "r"(a[3]), "r"(b[0]), "r"(b[1]));
}
__device__ __forceinline__ uint4 pack_bf16x8(float4 a, float4 b) {
    __nv_bfloat162 h0 = __floats2bfloat162_rn(a.x, a.y);
    __nv_bfloat162 h1 = __floats2bfloat162_rn(a.z, a.w);
    __nv_bfloat162 h2 = __floats2bfloat162_rn(b.x, b.y);
    __nv_bfloat162 h3 = __floats2bfloat162_rn(b.z, b.w);
    uint4 u;
    u.x = *reinterpret_cast<uint32_t*>(&h0);
    u.y = *reinterpret_cast<uint32_t*>(&h1);
    u.z = *reinterpret_cast<uint32_t*>(&h2);
    u.w = *reinterpret_cast<uint32_t*>(&h3);
    return u;
}

// ---------------- fused prep kernel (init + wconv + a1n + count) ----------------
#define PREP_WCONV_B 1
#define PREP_A1N_B   257
#define PREP_CNT_B   6507
#define PREP_GRID    8461

__global__ void prep_kernel(const float* __restrict__ feat, const float* __restrict__ r_vec,
                            const float* __restrict__ aw,
                            const float* __restrict__ fw1, const float* __restrict__ fw2,
                            const int* __restrict__ inst) {
    int b = blockIdx.x;
    int tid = threadIdx.x;
    if (b == 0) {
        if (tid < 2) g_w[tid] = 0.f;
        if (tid == 0) g_bar = 0u;
        if (tid < SCAN_BLOCKS) g_desc[tid] = 0ull;
        if (tid < 32) {
            int t = tid;
            float nre[4], nim[4];
#pragma unroll
            for (int r = 0; r < 4; r++) {
                float re = r_vec[r * 64 + t * 2];
                float im = r_vec[r * 64 + t * 2 + 1];
                float inv = rsqrtf(re * re + im * im);
                nre[r] = re * inv;
                nim[r] = im * inv;
            }
#pragma unroll
            for (int m = 0; m < 2; m++) {
                int a = 2 * m + 1, c = 2 * m;
                g_fr[m][2][t][0] = 1.f; g_fr[m][2][t][1] = 0.f;
                g_fr[m][1][t][0] = nre[a]; g_fr[m][1][t][1] = nim[a];
                g_fr[m][0][t][0] = nre[a] * nre[c] - nim[a] * nim[c];
                g_fr[m][0][t][1] = nre[a] * nim[c] + nim[a] * nre[c];
            }
        }
    } else if (b < PREP_A1N_B) {
        int i = (b - PREP_WCONV_B) * 256 + tid;
        if (i < 256 * 256) g_fw1b[i] = __float2bfloat16(fw1[i]);
        if (i < 128 * 256) g_fw2b[i] = __float2bfloat16(fw2[i]);
    } else if (b < PREP_CNT_B) {
        int gw = (b - PREP_A1N_B) * 8 + (tid >> 5);
        int lane = tid & 31;
        if (gw < NN) {
            float2 d = reinterpret_cast<const float2*>(feat)[gw * 32 + lane];
            float p[4];
#pragma unroll
            for (int h = 0; h < 4; h++) {
                float v = aw[h * 64 + 2 * lane] * d.x + aw[h * 64 + 2 * lane + 1] * d.y;
                p[h] = wredsum(v);
            }
            if (lane == 0) {
                float4 r;
                r.x = celu3f(p[0]); r.y = celu3f(p[1]); r.z = celu3f(p[2]); r.w = celu3f(p[3]);
                reinterpret_cast<float4*>(g_a1n)[gw] = r;
            }
        }
    } else {
        int idx = (b - PREP_CNT_B) * 256 + tid;
        if (idx < TOT_E) {
            int m = idx >= EE;
            int e = idx - m * EE;
            int seg = inst[(size_t)m * EE * 3 + (size_t)e * 3];
            atomicAdd(&g_counts[m * NN + seg], 1);
        }
    }
}

// ---------------- single-kernel scan (decoupled lookback) ----------------
// Also re-zeroes g_counts so no memset is needed next call.
__global__ void scan_kernel() {
    __shared__ int s[1024];
    __shared__ int exc_s;
    int t = threadIdx.x, b = blockIdx.x;
    int i = b * 1024 + t;
    int v = (i < TOT_N) ? g_counts[i] : 0;
    if (i < TOT_N) g_counts[i] = 0;
    s[t] = v;
    __syncthreads();
    for (int off = 1; off < 1024; off <<= 1) {
        int x = (t >= off) ? s[t - off] : 0;
        __syncthreads();
        s[t] += x;
        __syncthreads();
    }
    int incl = s[t];
    int total = s[1023];
    if (t == 0) {
        *((volatile unsigned long long*)&g_desc[b]) = (1ull << 32) | (unsigned)total;
        int run = 0;
        for (int p = b - 1; p >= 0; p--) {
            unsigned long long d;
            do { d = *((volatile unsigned long long*)&g_desc[p]); } while ((d >> 32) == 0ull);
            run += (int)(unsigned)d;
            if ((d >> 32) == 2ull) break;
        }
        *((volatile unsigned long long*)&g_desc[b]) = (2ull << 32) | (unsigned)(run + total);
        exc_s = run;
    }
    __syncthreads();
    int e = exc_s;
    if (i < TOT_N) {
        int o = e + incl - v;
        g_offsets[i] = o;
        g_cursor[i] = o;
    }
    if (t == 0 && b == SCAN_BLOCKS - 1) g_offsets[TOT_N] = e + total;
}

// Scatter (n1,n2) into CSR order (n0 implicit = segment id).
__global__ void scatter_kernel(const int* __restrict__ inst) {
    int idx = blockIdx.x * blockDim.x + threadIdx.x;
    if (idx >= TOT_E) return;
    int m = idx >= EE;
    int e = idx - m * EE;
    const int* ip = inst + (size_t)m * EE * 3 + (size_t)e * 3;
    int i0 = ip[0], i1 = ip[1], i2 = ip[2];
    int pos = atomicAdd(&g_cursor[m * NN + i0], 1);
    g_einst[pos] = make_int2(i1, i2);
}

// FUSED node kernel: one warp per (path, node); 2x 16-lane subgroups.
__global__ __launch_bounds__(256) void node_fused_kernel(
    const float* __restrict__ feat, const float* __restrict__ attn2) {
    int gw = (blockIdx.x * blockDim.x + threadIdx.x) >> 5;
    int lane = threadIdx.x & 31;
    if (gw >= TOT_N) return;
    int m = gw >= NN;
    int n = gw - m * NN;
    int start = g_offsets[gw];
    int deg = g_offsets[gw + 1] - start;
    int sub = lane >> 4;
    int li = lane & 15;

    float2 fr0[3], fr1[3];
#pragma unroll
    for (int p = 0; p < 3; p++) {
        fr0[p] = *reinterpret_cast<const float2*>(&g_fr[m][p][2 * li][0]);
        fr1[p] = *reinterpret_cast<const float2*>(&g_fr[m][p][2 * li + 1][0]);
    }
    float4 at2[4];
#pragma unroll
    for (int h = 0; h < 4; h++)
        at2[h] = *reinterpret_cast<const float4*>(attn2 + h * 64 + 4 * li);
    float4 a1q = *reinterpret_cast<const float4*>(g_a1n + n * 4);
    float a1a[4] = {a1q.x, a1q.y, a1q.z, a1q.w};

    // hoisted n0 (p=0) contribution
    float4 d0 = *reinterpret_cast<const float4*>(feat + (size_t)n * 64 + 4 * li);
    float c_re0 = d0.x * fr0[0].x - d0.y * fr0[0].y;
    float c_im0 = d0.x * fr0[0].y + d0.y * fr0[0].x;
    float c_re1 = d0.z * fr1[0].x - d0.w * fr1[0].y;
    float c_im1 = d0.z * fr1[0].y + d0.w * fr1[0].x;

    float acc[4][4];
    float den[4] = {0.f, 0.f, 0.f, 0.f};
#pragma unroll
    for (int h = 0; h < 4; h++)
#pragma unroll
        for (int j = 0; j < 4; j++) acc[h][j] = 0.f;

    int padded = (deg + 1) & ~1;
    for (int i = sub; i < padded; i += 2) {
        bool act = i < deg;
        int2 nd = g_einst[start + (act ? i : 0)];
        float mre0 = c_re0, mim0 = c_im0, mre1 = c_re1, mim1 = c_im1;
        {
            float4 d = *reinterpret_cast<const float4*>(feat + (size_t)nd.x * 64 + 4 * li);
            mre0 += d.x * fr0[1].x - d.y * fr0[1].y;
            mim0 += d.x * fr0[1].y + d.y * fr0[1].x;
            mre1 += d.z * fr1[1].x - d.w * fr1[1].y;
            mim1 += d.z * fr1[1].y + d.w * fr1[1].x;
        }
        {
            float4 d = *reinterpret_cast<const float4*>(feat + (size_t)nd.y * 64 + 4 * li);
            mre0 += d.x * fr0[2].x - d.y * fr0[2].y;
            mim0 += d.x * fr0[2].y + d.y * fr0[2].x;
            mre1 += d.z * fr1[2].x - d.w * fr1[2].y;
            mim1 += d.z * fr1[2].y + d.w * fr1[2].x;
        }
        float ef[4];
        ef[0] = gatef(mre0 * (1.f / 3.f));
        ef[1] = gatef(mim0 * (1.f / 3.f));
        ef[2] = gatef(mre1 * (1.f / 3.f));
        ef[3] = gatef(mim1 * (1.f / 3.f));
        float ph[4];
#pragma unroll
        for (int h = 0; h < 4; h++) {
            ph[h] = at2[h].x * ef[0] + at2[h].y * ef[1]
                  + at2[h].z * ef[2] + at2[h].w * ef[3];
#pragma unroll
            for (int o = 8; o; o >>= 1) ph[h] += __shfl_xor_sync(0xffffffffu, ph[h], o);
        }
#pragma unroll
        for (int h = 0; h < 4; h++) {
            float a = celu3f(a1a[h] + ph[h]);
            float wv = act ? __expf(a) : 0.f;
            den[h] += wv;
            acc[h][0] += wv * ef[0];
            acc[h][1] += wv * ef[1];
            acc[h][2] += wv * ef[2];
            acc[h][3] += wv * ef[3];
        }
    }
#pragma unroll
    for (int h = 0; h < 4; h++) {
        den[h] += __shfl_xor_sync(0xffffffffu, den[h], 16);
#pragma unroll
        for (int j = 0; j < 4; j++)
            acc[h][j] += __shfl_xor_sync(0xffffffffu, acc[h][j], 16);
    }
    if (sub == 0) {
        float* zr = g_z + (size_t)n * 512 + m * 256;
#pragma unroll
        for (int h = 0; h < 4; h++) {
            float inv = (deg > 0) ? __fdividef(1.f, den[h]) : 0.f;
            float z0 = celu3f(acc[h][0] * inv);
            float z1 = celu3f(acc[h][1] * inv);
            float z2 = celu3f(acc[h][2] * inv);
            float z3 = celu3f(acc[h][3] * inv);
            *reinterpret_cast<float4*>(zr + h * 64 + 4 * li) = make_float4(z0, z1, z2, z3);
        }
    }
}

// ---------------- persistent MLP + grid barrier + final blend ----------------
#define P_SSTRIDE 528
#define P_OFF_W2  135168
#define P_OFF_A   202752
#define P_OFF_FB1 219648
#define P_OFF_FB2 220672
#define P_OFF_FW3 221184
#define P_OFF_RED 221696
#define P_SMEM    221824
#define N_TILES   ((ROWS_TOT + 31) / 32)     // 3125

__global__ __launch_bounds__(512, 1) void mlp_persist_kernel(
    const float* __restrict__ fb1, const float* __restrict__ fb2,
    const float* __restrict__ fw3, float* __restrict__ out) {
    extern __shared__ char smem[];
    char* sw1 = smem;
    char* sw2 = smem + P_OFF_W2;
    char* sa  = smem + P_OFF_A;
    float* fb1s = reinterpret_cast<float*>(smem + P_OFF_FB1);
    float* fb2s = reinterpret_cast<float*>(smem + P_OFF_FB2);
    float* fw3s = reinterpret_cast<float*>(smem + P_OFF_FW3);
    float* red  = reinterpret_cast<float*>(smem + P_OFF_RED);

    uint32_t sw1_u = smem_to_u32(smem);
    uint32_t sw2_u = sw1_u + P_OFF_W2;
    uint32_t sa_u  = sw1_u + P_OFF_A;

    int tid = threadIdx.x;
    int wid = tid >> 5;
    int lane = tid & 31;
    int wm = wid >> 3;
    int wn = wid & 7;
    int m_base = wm * 16;
    int g = lane >> 2;
    int tig = lane & 3;

    for (int idx = tid; idx < 8192; idx += 512) {
        int r = idx >> 5, c = idx & 31;
        uint4 v = *reinterpret_cast<const uint4*>(g_fw1b + r * 256 + c * 8);
        *reinterpret_cast<uint4*>(sw1 + r * P_SSTRIDE + c * 16) = v;
    }
    for (int idx = tid; idx < 4096; idx += 512) {
        int r = idx >> 5, c = idx & 31;
        uint4 v = *reinterpret_cast<const uint4*>(g_fw2b + r * 256 + c * 8);
        *reinterpret_cast<uint4*>(sw2 + r * P_SSTRIDE + c * 16) = v;
    }
    for (int i = tid; i < 256; i += 512) fb1s[i] = fb1[i];
    for (int i = tid; i < 128; i += 512) { fb2s[i] = fb2[i]; fw3s[i] = fw3[i]; }

    int r0 = (tid * 2) >> 5,     c0 = (tid * 2) & 31;
    int r1 = (tid * 2 + 1) >> 5, c1 = (tid * 2 + 1) & 31;

    {
        int rowbase = blockIdx.x * 32;
        float4 a0 = make_float4(0, 0, 0, 0), b0 = a0, a1 = a0, b1 = a0;
        if (rowbase + r0 < ROWS_TOT) {
            const float4* zp = reinterpret_cast<const float4*>(g_z + (size_t)(rowbase + r0) * 256 + c0 * 8);
            a0 = zp[0]; b0 = zp[1];
        }
        if (rowbase + r1 < ROWS_TOT) {
            const float4* zp = reinterpret_cast<const float4*>(g_z + (size_t)(rowbase + r1) * 256 + c1 * 8);
            a1 = zp[0]; b1 = zp[1];
        }
        *reinterpret_cast<uint4*>(sa + r0 * P_SSTRIDE + c0 * 16) = pack_bf16x8(a0, b0);
        *reinterpret_cast<uint4*>(sa + r1 * P_SSTRIDE + c1 * 16) = pack_bf16x8(a1, b1);
    }
    __syncthreads();

    int arow  = m_base + (lane & 15);
    int acol8 = ((lane >> 4) & 1) * 8;
    int brow1 = wn * 32 + ((lane >> 4) & 1) * 8 + (lane & 7);
    int brow2 = wn * 16 + ((lane >> 4) & 1) * 8 + (lane & 7);
    int bcol8 = ((lane >> 3) & 1) * 8;

    float ws0 = 0.f, ws1 = 0.f;

    for (int t = blockIdx.x; t < N_TILES; t += MLP_GRID) {
        int rowbase = t * 32;
        int tn = t + MLP_GRID;
        bool has_next = tn < N_TILES;

        float4 pa0 = make_float4(0, 0, 0, 0), pb0 = pa0, pa1 = pa0, pb1 = pa0;
        if (has_next) {
            int nb = tn * 32;
            if (nb + r0 < ROWS_TOT) {
                const float4* zp = reinterpret_cast<const float4*>(g_z + (size_t)(nb + r0) * 256 + c0 * 8);
                pa0 = zp[0]; pb0 = zp[1];
            }
            if (nb + r1 < ROWS_TOT) {
                const float4* zp = reinterpret_cast<const float4*>(g_z + (size_t)(nb + r1) * 256 + c1 * 8);
                pa1 = zp[0]; pb1 = zp[1];
            }
        }

        float acc[4][4];
#pragma unroll
        for (int nt = 0; nt < 4; nt++)
#pragma unroll
            for (int c = 0; c < 4; c++) acc[nt][c] = 0.f;
#pragma unroll
        for (int k = 0; k < 256; k += 16) {
            uint32_t af[4];
            ldsm_x4(sa_u + arow * P_SSTRIDE + (k + acol8) * 2, af);
#pragma unroll
            for (int np = 0; np < 2; np++) {
                uint32_t bf[4];
                ldsm_x4(sw1_u + (brow1 + np * 16) * P_SSTRIDE + (k + bcol8) * 2, bf);
                mma_bf16(acc[np * 2],     af, bf);
                mma_bf16(acc[np * 2 + 1], af, bf + 2);
            }
        }
        __syncthreads();

#pragma unroll
        for (int nt = 0; nt < 4; nt++) {
            int row = m_base + g;
            int col = wn * 32 + nt * 8 + tig * 2;
            float b0 = fb1s[col], b1 = fb1s[col + 1];
            float t0 = celu3f(acc[nt][0] + b0);
            float t1 = celu3f(acc[nt][1] + b1);
            float t2 = celu3f(acc[nt][2] + b0);
            float t3 = celu3f(acc[nt][3] + b1);
            __nv_bfloat162 p01 = __floats2bfloat162_rn(t0, t1);
            __nv_bfloat162 p23 = __floats2bfloat162_rn(t2, t3);
            *reinterpret_cast<uint32_t*>(sa + row * P_SSTRIDE + col * 2) =
                *reinterpret_cast<uint32_t*>(&p01);
            *reinterpret_cast<uint32_t*>(sa + (row + 8) * P_SSTRIDE + col * 2) =
                *reinterpret_cast<uint32_t*>(&p23);
        }
        __syncthreads();

        float acc2[2][4];
#pragma unroll
        for (int nt = 0; nt < 2; nt++)
#pragma unroll
            for (int c = 0; c < 4; c++) acc2[nt][c] = 0.f;
#pragma unroll
        for (int k = 0; k < 256; k += 16) {
            uint32_t af[4];
            ldsm_x4(sa_u + arow * P_SSTRIDE + (k + acol8) * 2, af);
            uint32_t bf[4];
            ldsm_x4(sw2_u + brow2 * P_SSTRIDE + (k + bcol8) * 2, bf);
            mma_bf16(acc2[0], af, bf);
            mma_bf16(acc2[1], af, bf + 2);
        }

        {
            int row0 = rowbase + m_base + g;
            int row1 = row0 + 8;
            float sA = 0.f, sB = 0.f;
#pragma unroll
            for (int nt = 0; nt < 2; nt++) {
                int col = wn * 16 + nt * 8 + tig * 2;
                float b0 = fb2s[col], b1 = fb2s[col + 1];
                float w0 = fw3s[col], w1 = fw3s[col + 1];
                sA += celu3f(acc2[nt][0] + b0) * w0 + celu3f(acc2[nt][1] + b1) * w1;
                sB += celu3f(acc2[nt][2] + b0) * w0 + celu3f(acc2[nt][3] + b1) * w1;
            }
            int p = g & 1;
            float s = 0.f;
            if (row0 < ROWS_TOT) s += sA;
            if (row1 < ROWS_TOT) s += sB;
            if (p) ws1 += s; else ws0 += s;
        }
        __syncthreads();

        if (has_next) {
            *reinterpret_cast<uint4*>(sa + r0 * P_SSTRIDE + c0 * 16) = pack_bf16x8(pa0, pb0);
            *reinterpret_cast<uint4*>(sa + r1 * P_SSTRIDE + c1 * 16) = pack_bf16x8(pa1, pb1);
        }
        __syncthreads();
    }

    ws0 = wredsum(ws0);
    ws1 = wredsum(ws1);
    if (lane == 0) { red[wid * 2] = ws0; red[wid * 2 + 1] = ws1; }
    __syncthreads();
    if (tid == 0) {
        float s0 = 0.f, s1 = 0.f;
#pragma unroll
        for (int w = 0; w < 16; w++) { s0 += red[w * 2]; s1 += red[w * 2 + 1]; }
        atomicAdd(&g_w[0], s0);
        atomicAdd(&g_w[1], s1);
    }

    // ---- grid barrier (all 148 CTAs resident at 1 CTA/SM) ----
    __syncthreads();
    if (tid == 0) {
        __threadfence();
        atomicAdd(&g_bar, 1u);
        while (*((volatile unsigned int*)&g_bar) < (unsigned)MLP_GRID) {}
    }
    __syncthreads();
    __threadfence();

    // ---- beta + final blend (g_z mostly L2-warm) ----
    float w0 = *((volatile float*)&g_w[0]) * (1.f / (float)NN);
    float w1 = *((volatile float*)&g_w[1]) * (1.f / (float)NN);
    float mx = fmaxf(w0, w1);
    float e0 = expf(w0 - mx), e1 = expf(w1 - mx);
    float binv = 1.f / (e0 + e1);
    float beta0 = e0 * binv, beta1 = e1 * binv;

    for (int idx = blockIdx.x * 512 + tid; idx < NN * 64; idx += MLP_GRID * 512) {
        int n = idx >> 6;
        int q = idx & 63;
        float4 z0 = reinterpret_cast<const float4*>(g_z)[(size_t)n * 128 + q];
        float4 z1 = reinterpret_cast<const float4*>(g_z)[(size_t)n * 128 + 64 + q];
        float4 o;
        o.x = beta0 * z0.x + beta1 * z1.x;
        o.y = beta0 * z0.y + beta1 * z1.y;
        o.z = beta0 * z0.z + beta1 * z1.z;
        o.w = beta0 * z0.w + beta1 * z1.w;
        reinterpret_cast<float4*>(out)[idx] = o;
    }
}

// ---------------- launch ----------------
extern "C" void kernel_launch(void* const* d_in, const int* in_sizes, int n_in,
                              void* d_out, int out_size) {
    const float* feat    = (const float*)d_in[0];
    const float* r_vec   = (const float*)d_in[1];
    const float* attn1_w = (const float*)d_in[2];
    const float* attn2   = (const float*)d_in[3];
    const float* fw1     = (const float*)d_in[4];
    const float* fb1     = (const float*)d_in[5];
    const float* fw2     = (const float*)d_in[6];
    const float* fb2     = (const float*)d_in[7];
    const float* fw3     = (const float*)d_in[8];
    const int*   inst    = (const int*)d_in[9];
    float* out = (float*)d_out;

    prep_kernel<<<PREP_GRID, 256>>>(feat, r_vec, attn1_w, fw1, fw2, inst);
    scan_kernel<<<SCAN_BLOCKS, 1024>>>();
    scatter_kernel<<<(TOT_E + 255) / 256, 256>>>(inst);
    node_fused_kernel<<<(TOT_N * 32 + 255) / 256, 256>>>(feat, attn2);

    cudaFuncSetAttribute(mlp_persist_kernel, cudaFuncAttributeMaxDynamicSharedMemorySize, P_SMEM);
    mlp_persist_kernel<<<MLP_GRID, 512, P_SMEM>>>(fb1, fb2, fw3, out);
}

// round 12
// speedup vs baseline: 1.1200x; 1.1200x over previous
#include <cuda_runtime.h>
#include <cuda_bf16.h>
#include <math.h>
#include <float.h>
#include <stdint.h>

// Problem constants (fixed by dataset)
#define NN 50000
#define HH 64
#define EE 250000
#define HEADS 4
#define TOT_E (2 * EE)             // edges across both paths
#define TOT_N (2 * NN)             // segments across both paths
#define ROWS_TOT (NN * 2)          // 100000 MLP rows (N nodes x 2 paths)
#define SCAN_BLOCKS ((TOT_N + 1023) / 1024)   // 98
#define MLP_GRID  148

// ---------------- scratch (static device memory; no allocs) ----------------
__device__ float g_fr[2][3][32][2];
__device__ float g_a1n[NN * 4];
__device__ int   g_counts[TOT_N];          // re-zeroed by scan each run
__device__ int   g_offsets[TOT_N + 1];
__device__ int   g_cursor[TOT_N];
__device__ unsigned long long g_desc[SCAN_BLOCKS];
__device__ unsigned int g_bar;
__device__ __align__(8) int2 g_einst[TOT_E];  // CSR-sorted (n1,n2) per edge
__device__ float g_z[(size_t)NN * 512];       // fp32 rows: row (2n+m) x 256
__device__ __align__(16) __nv_bfloat16 g_fw1b[256 * 256];
__device__ __align__(16) __nv_bfloat16 g_fw2b[128 * 256];
__device__ float g_w[2];

// ---------------- helpers ----------------
__device__ __forceinline__ float celu3f(float x) {
    return x > 0.f ? x : 3.f * (__expf(x * (1.f / 3.f)) - 1.f);
}
__device__ __forceinline__ float gatef(float x) {
    float e1 = __expf(x * (1.f / 3.f));
    float e3 = e1 * e1 * e1;                    // exp(x)
    float s  = __fdividef(e3, e3 + 1.f);        // sigmoid(x)
    float c1 = x > 0.f ? x : 3.f * (e1 - 1.f);  // celu3(x)
    float se = c1 * s;
    return se > 0.f ? se : 3.f * (__expf(se * (1.f / 3.f)) - 1.f);
}
__device__ __forceinline__ float wredsum(float v) {
#pragma unroll
    for (int o = 16; o; o >>= 1) v += __shfl_xor_sync(0xffffffffu, v, o);
    return v;
}
__device__ __forceinline__ uint32_t smem_to_u32(const void* p) {
    uint32_t a;
    asm("{ .reg .u64 t; cvta.to.shared.u64 t, %1; cvt.u32.u64 %0, t; }" : "=r"(a) : "l"(p));
    return a;
}
__device__ __forceinline__ void ldsm_x4(uint32_t addr, uint32_t* r) {
    asm volatile("ldmatrix.sync.aligned.m8n8.x4.shared.b16 {%0,%1,%2,%3}, [%4];"
                 : "=r"(r[0]), "=r"(r[1]), "=r"(r[2]), "=r"(r[3]) : "r"(addr));
}
__device__ __forceinline__ void mma_bf16(float* d, const uint32_t* a, const uint32_t* b) {
    asm volatile(
        "mma.sync.aligned.m16n8k16.row.col.f32.bf16.bf16.f32 "
        "{%0,%1,%2,%3}, {%4,%5,%6,%7}, {%8,%9}, {%0,%1,%2,%3};"
        : "+f"(d[0]), "+f"(d[1]), "+f"(d[2]), "+f"(d[3])
        : "r"(a[0]), "r"(a[1]), "r"(a[2]), "r"(a[3]), "r"(b[0]), "r"(b[1]));
}
__device__ __forceinline__ uint4 pack_bf16x8(float4 a, float4 b) {
    __nv_bfloat162 h0 = __floats2bfloat162_rn(a.x, a.y);
    __nv_bfloat162 h1 = __floats2bfloat162_rn(a.z, a.w);
    __nv_bfloat162 h2 = __floats2bfloat162_rn(b.x, b.y);
    __nv_bfloat162 h3 = __floats2bfloat162_rn(b.z, b.w);
    uint4 u;
    u.x = *reinterpret_cast<uint32_t*>(&h0);
    u.y = *reinterpret_cast<uint32_t*>(&h1);
    u.z = *reinterpret_cast<uint32_t*>(&h2);
    u.w = *reinterpret_cast<uint32_t*>(&h3);
    return u;
}

// ---------------- fused prep kernel (init + wconv + a1n + count) ----------------
#define PREP_WCONV_B 1
#define PREP_A1N_B   257
#define PREP_CNT_B   6507
#define PREP_GRID    8461

__global__ void prep_kernel(const float* __restrict__ feat, const float* __restrict__ r_vec,
                            const float* __restrict__ aw,
                            const float* __restrict__ fw1, const float* __restrict__ fw2,
                            const int* __restrict__ inst) {
    int b = blockIdx.x;
    int tid = threadIdx.x;
    if (b == 0) {
        if (tid < 2) g_w[tid] = 0.f;
        if (tid == 0) g_bar = 0u;
        if (tid < SCAN_BLOCKS) g_desc[tid] = 0ull;
        if (tid < 32) {
            int t = tid;
            float nre[4], nim[4];
#pragma unroll
            for (int r = 0; r < 4; r++) {
                float re = r_vec[r * 64 + t * 2];
                float im = r_vec[r * 64 + t * 2 + 1];
                float inv = rsqrtf(re * re + im * im);
                nre[r] = re * inv;
                nim[r] = im * inv;
            }
#pragma unroll
            for (int m = 0; m < 2; m++) {
                int a = 2 * m + 1, c = 2 * m;
                g_fr[m][2][t][0] = 1.f; g_fr[m][2][t][1] = 0.f;
                g_fr[m][1][t][0] = nre[a]; g_fr[m][1][t][1] = nim[a];
                g_fr[m][0][t][0] = nre[a] * nre[c] - nim[a] * nim[c];
                g_fr[m][0][t][1] = nre[a] * nim[c] + nim[a] * nre[c];
            }
        }
    } else if (b < PREP_A1N_B) {
        int i = (b - PREP_WCONV_B) * 256 + tid;
        if (i < 256 * 256) g_fw1b[i] = __float2bfloat16(fw1[i]);
        if (i < 128 * 256) g_fw2b[i] = __float2bfloat16(fw2[i]);
    } else if (b < PREP_CNT_B) {
        int gw = (b - PREP_A1N_B) * 8 + (tid >> 5);
        int lane = tid & 31;
        if (gw < NN) {
            float2 d = reinterpret_cast<const float2*>(feat)[gw * 32 + lane];
            float p[4];
#pragma unroll
            for (int h = 0; h < 4; h++) {
                float v = aw[h * 64 + 2 * lane] * d.x + aw[h * 64 + 2 * lane + 1] * d.y;
                p[h] = wredsum(v);
            }
            if (lane == 0) {
                float4 r;
                r.x = celu3f(p[0]); r.y = celu3f(p[1]); r.z = celu3f(p[2]); r.w = celu3f(p[3]);
                reinterpret_cast<float4*>(g_a1n)[gw] = r;
            }
        }
    } else {
        int idx = (b - PREP_CNT_B) * 256 + tid;
        if (idx < TOT_E) {
            int m = idx >= EE;
            int e = idx - m * EE;
            int seg = inst[(size_t)m * EE * 3 + (size_t)e * 3];
            atomicAdd(&g_counts[m * NN + seg], 1);
        }
    }
}

// ---------------- single-kernel scan (decoupled lookback) ----------------
__global__ void scan_kernel() {
    __shared__ int s[1024];
    __shared__ int exc_s;
    int t = threadIdx.x, b = blockIdx.x;
    int i = b * 1024 + t;
    int v = (i < TOT_N) ? g_counts[i] : 0;
    if (i < TOT_N) g_counts[i] = 0;
    s[t] = v;
    __syncthreads();
    for (int off = 1; off < 1024; off <<= 1) {
        int x = (t >= off) ? s[t - off] : 0;
        __syncthreads();
        s[t] += x;
        __syncthreads();
    }
    int incl = s[t];
    int total = s[1023];
    if (t == 0) {
        *((volatile unsigned long long*)&g_desc[b]) = (1ull << 32) | (unsigned)total;
        int run = 0;
        for (int p = b - 1; p >= 0; p--) {
            unsigned long long d;
            do { d = *((volatile unsigned long long*)&g_desc[p]); } while ((d >> 32) == 0ull);
            run += (int)(unsigned)d;
            if ((d >> 32) == 2ull) break;
        }
        *((volatile unsigned long long*)&g_desc[b]) = (2ull << 32) | (unsigned)(run + total);
        exc_s = run;
    }
    __syncthreads();
    int e = exc_s;
    if (i < TOT_N) {
        int o = e + incl - v;
        g_offsets[i] = o;
        g_cursor[i] = o;
    }
    if (t == 0 && b == SCAN_BLOCKS - 1) g_offsets[TOT_N] = e + total;
}

// Scatter (n1,n2) into CSR order (n0 implicit = segment id).
__global__ void scatter_kernel(const int* __restrict__ inst) {
    int idx = blockIdx.x * blockDim.x + threadIdx.x;
    if (idx >= TOT_E) return;
    int m = idx >= EE;
    int e = idx - m * EE;
    const int* ip = inst + (size_t)m * EE * 3 + (size_t)e * 3;
    int i0 = ip[0], i1 = ip[1], i2 = ip[2];
    int pos = atomicAdd(&g_cursor[m * NN + i0], 1);
    g_einst[pos] = make_int2(i1, i2);
}

// FUSED node kernel: one warp per (path, node); 2x 16-lane subgroups.
// attn2 staged in SMEM (frees 16 regs); launch_bounds caps regs at 64 -> 4 CTAs/SM.
__global__ __launch_bounds__(256, 4) void node_fused_kernel(
    const float* __restrict__ feat, const float* __restrict__ attn2) {
    __shared__ float s_at2[256];
    if (threadIdx.x < 256) s_at2[threadIdx.x] = attn2[threadIdx.x];
    __syncthreads();

    int gw = (blockIdx.x * blockDim.x + threadIdx.x) >> 5;
    int lane = threadIdx.x & 31;
    if (gw >= TOT_N) return;
    int m = gw >= NN;
    int n = gw - m * NN;
    int start = g_offsets[gw];
    int deg = g_offsets[gw + 1] - start;
    int sub = lane >> 4;
    int li = lane & 15;

    float2 fr0[3], fr1[3];
#pragma unroll
    for (int p = 0; p < 3; p++) {
        fr0[p] = *reinterpret_cast<const float2*>(&g_fr[m][p][2 * li][0]);
        fr1[p] = *reinterpret_cast<const float2*>(&g_fr[m][p][2 * li + 1][0]);
    }
    float4 a1q = *reinterpret_cast<const float4*>(g_a1n + n * 4);
    float a1a[4] = {a1q.x, a1q.y, a1q.z, a1q.w};

    // hoisted n0 (p=0) contribution
    float4 d0 = *reinterpret_cast<const float4*>(feat + (size_t)n * 64 + 4 * li);
    float c_re0 = d0.x * fr0[0].x - d0.y * fr0[0].y;
    float c_im0 = d0.x * fr0[0].y + d0.y * fr0[0].x;
    float c_re1 = d0.z * fr1[0].x - d0.w * fr1[0].y;
    float c_im1 = d0.z * fr1[0].y + d0.w * fr1[0].x;

    float acc[4][4];
    float den[4] = {0.f, 0.f, 0.f, 0.f};
#pragma unroll
    for (int h = 0; h < 4; h++)
#pragma unroll
        for (int j = 0; j < 4; j++) acc[h][j] = 0.f;

    int padded = (deg + 1) & ~1;
    // prefetch first edge indices
    int2 nd = (sub < padded) ? g_einst[start + ((sub < deg) ? sub : 0)] : make_int2(0, 0);
    for (int i = sub; i < padded; i += 2) {
        bool act = i < deg;
        int2 cur = nd;
        int inext = i + 2;
        if (inext < padded)
            nd = g_einst[start + ((inext < deg) ? inext : 0)];
        float mre0 = c_re0, mim0 = c_im0, mre1 = c_re1, mim1 = c_im1;
        {
            float4 d = *reinterpret_cast<const float4*>(feat + (size_t)cur.x * 64 + 4 * li);
            mre0 += d.x * fr0[1].x - d.y * fr0[1].y;
            mim0 += d.x * fr0[1].y + d.y * fr0[1].x;
            mre1 += d.z * fr1[1].x - d.w * fr1[1].y;
            mim1 += d.z * fr1[1].y + d.w * fr1[1].x;
        }
        {
            float4 d = *reinterpret_cast<const float4*>(feat + (size_t)cur.y * 64 + 4 * li);
            mre0 += d.x * fr0[2].x - d.y * fr0[2].y;
            mim0 += d.x * fr0[2].y + d.y * fr0[2].x;
            mre1 += d.z * fr1[2].x - d.w * fr1[2].y;
            mim1 += d.z * fr1[2].y + d.w * fr1[2].x;
        }
        float ef[4];
        ef[0] = gatef(mre0 * (1.f / 3.f));
        ef[1] = gatef(mim0 * (1.f / 3.f));
        ef[2] = gatef(mre1 * (1.f / 3.f));
        ef[3] = gatef(mim1 * (1.f / 3.f));
        float ph[4];
#pragma unroll
        for (int h = 0; h < 4; h++) {
            float4 a2v = *reinterpret_cast<const float4*>(&s_at2[h * 64 + 4 * li]);
            ph[h] = a2v.x * ef[0] + a2v.y * ef[1] + a2v.z * ef[2] + a2v.w * ef[3];
#pragma unroll
            for (int o = 8; o; o >>= 1) ph[h] += __shfl_xor_sync(0xffffffffu, ph[h], o);
        }
#pragma unroll
        for (int h = 0; h < 4; h++) {
            float a = celu3f(a1a[h] + ph[h]);
            float wv = act ? __expf(a) : 0.f;
            den[h] += wv;
            acc[h][0] += wv * ef[0];
            acc[h][1] += wv * ef[1];
            acc[h][2] += wv * ef[2];
            acc[h][3] += wv * ef[3];
        }
    }
#pragma unroll
    for (int h = 0; h < 4; h++) {
        den[h] += __shfl_xor_sync(0xffffffffu, den[h], 16);
#pragma unroll
        for (int j = 0; j < 4; j++)
            acc[h][j] += __shfl_xor_sync(0xffffffffu, acc[h][j], 16);
    }
    if (sub == 0) {
        float* zr = g_z + (size_t)n * 512 + m * 256;
#pragma unroll
        for (int h = 0; h < 4; h++) {
            float inv = (deg > 0) ? __fdividef(1.f, den[h]) : 0.f;
            float z0 = celu3f(acc[h][0] * inv);
            float z1 = celu3f(acc[h][1] * inv);
            float z2 = celu3f(acc[h][2] * inv);
            float z3 = celu3f(acc[h][3] * inv);
            *reinterpret_cast<float4*>(zr + h * 64 + 4 * li) = make_float4(z0, z1, z2, z3);
        }
    }
}

// ---------------- persistent MLP + grid barrier + final blend ----------------
#define P_SSTRIDE 528
#define P_OFF_W2  135168
#define P_OFF_A   202752
#define P_OFF_FB1 219648
#define P_OFF_FB2 220672
#define P_OFF_FW3 221184
#define P_OFF_RED 221696
#define P_SMEM    221824
#define N_TILES   ((ROWS_TOT + 31) / 32)     // 3125

__global__ __launch_bounds__(512, 1) void mlp_persist_kernel(
    const float* __restrict__ fb1, const float* __restrict__ fb2,
    const float* __restrict__ fw3, float* __restrict__ out) {
    extern __shared__ char smem[];
    char* sw1 = smem;
    char* sw2 = smem + P_OFF_W2;
    char* sa  = smem + P_OFF_A;
    float* fb1s = reinterpret_cast<float*>(smem + P_OFF_FB1);
    float* fb2s = reinterpret_cast<float*>(smem + P_OFF_FB2);
    float* fw3s = reinterpret_cast<float*>(smem + P_OFF_FW3);
    float* red  = reinterpret_cast<float*>(smem + P_OFF_RED);

    uint32_t sw1_u = smem_to_u32(smem);
    uint32_t sw2_u = sw1_u + P_OFF_W2;
    uint32_t sa_u  = sw1_u + P_OFF_A;

    int tid = threadIdx.x;
    int wid = tid >> 5;
    int lane = tid & 31;
    int wm = wid >> 3;
    int wn = wid & 7;
    int m_base = wm * 16;
    int g = lane >> 2;
    int tig = lane & 3;

    for (int idx = tid; idx < 8192; idx += 512) {
        int r = idx >> 5, c = idx & 31;
        uint4 v = *reinterpret_cast<const uint4*>(g_fw1b + r * 256 + c * 8);
        *reinterpret_cast<uint4*>(sw1 + r * P_SSTRIDE + c * 16) = v;
    }
    for (int idx = tid; idx < 4096; idx += 512) {
        int r = idx >> 5, c = idx & 31;
        uint4 v = *reinterpret_cast<const uint4*>(g_fw2b + r * 256 + c * 8);
        *reinterpret_cast<uint4*>(sw2 + r * P_SSTRIDE + c * 16) = v;
    }
    for (int i = tid; i < 256; i += 512) fb1s[i] = fb1[i];
    for (int i = tid; i < 128; i += 512) { fb2s[i] = fb2[i]; fw3s[i] = fw3[i]; }

    int r0 = (tid * 2) >> 5,     c0 = (tid * 2) & 31;
    int r1 = (tid * 2 + 1) >> 5, c1 = (tid * 2 + 1) & 31;

    {
        int rowbase = blockIdx.x * 32;
        float4 a0 = make_float4(0, 0, 0, 0), b0 = a0, a1 = a0, b1 = a0;
        if (rowbase + r0 < ROWS_TOT) {
            const float4* zp = reinterpret_cast<const float4*>(g_z + (size_t)(rowbase + r0) * 256 + c0 * 8);
            a0 = zp[0]; b0 = zp[1];
        }
        if (rowbase + r1 < ROWS_TOT) {
            const float4* zp = reinterpret_cast<const float4*>(g_z + (size_t)(rowbase + r1) * 256 + c1 * 8);
            a1 = zp[0]; b1 = zp[1];
        }
        *reinterpret_cast<uint4*>(sa + r0 * P_SSTRIDE + c0 * 16) = pack_bf16x8(a0, b0);
        *reinterpret_cast<uint4*>(sa + r1 * P_SSTRIDE + c1 * 16) = pack_bf16x8(a1, b1);
    }
    __syncthreads();

    int arow  = m_base + (lane & 15);
    int acol8 = ((lane >> 4) & 1) * 8;
    int brow1 = wn * 32 + ((lane >> 4) & 1) * 8 + (lane & 7);
    int brow2 = wn * 16 + ((lane >> 4) & 1) * 8 + (lane & 7);
    int bcol8 = ((lane >> 3) & 1) * 8;

    float ws0 = 0.f, ws1 = 0.f;

    for (int t = blockIdx.x; t < N_TILES; t += MLP_GRID) {
        int rowbase = t * 32;
        int tn = t + MLP_GRID;
        bool has_next = tn < N_TILES;

        float4 pa0 = make_float4(0, 0, 0, 0), pb0 = pa0, pa1 = pa0, pb1 = pa0;
        if (has_next) {
            int nb = tn * 32;
            if (nb + r0 < ROWS_TOT) {
                const float4* zp = reinterpret_cast<const float4*>(g_z + (size_t)(nb + r0) * 256 + c0 * 8);
                pa0 = zp[0]; pb0 = zp[1];
            }
            if (nb + r1 < ROWS_TOT) {
                const float4* zp = reinterpret_cast<const float4*>(g_z + (size_t)(nb + r1) * 256 + c1 * 8);
                pa1 = zp[0]; pb1 = zp[1];
            }
        }

        float acc[4][4];
#pragma unroll
        for (int nt = 0; nt < 4; nt++)
#pragma unroll
            for (int c = 0; c < 4; c++) acc[nt][c] = 0.f;
#pragma unroll
        for (int k = 0; k < 256; k += 16) {
            uint32_t af[4];
            ldsm_x4(sa_u + arow * P_SSTRIDE + (k + acol8) * 2, af);
#pragma unroll
            for (int np = 0; np < 2; np++) {
                uint32_t bf[4];
                ldsm_x4(sw1_u + (brow1 + np * 16) * P_SSTRIDE + (k + bcol8) * 2, bf);
                mma_bf16(acc[np * 2],     af, bf);
                mma_bf16(acc[np * 2 + 1], af, bf + 2);
            }
        }
        __syncthreads();

#pragma unroll
        for (int nt = 0; nt < 4; nt++) {
            int row = m_base + g;
            int col = wn * 32 + nt * 8 + tig * 2;
            float b0 = fb1s[col], b1 = fb1s[col + 1];
            float t0 = celu3f(acc[nt][0] + b0);
            float t1 = celu3f(acc[nt][1] + b1);
            float t2 = celu3f(acc[nt][2] + b0);
            float t3 = celu3f(acc[nt][3] + b1);
            __nv_bfloat162 p01 = __floats2bfloat162_rn(t0, t1);
            __nv_bfloat162 p23 = __floats2bfloat162_rn(t2, t3);
            *reinterpret_cast<uint32_t*>(sa + row * P_SSTRIDE + col * 2) =
                *reinterpret_cast<uint32_t*>(&p01);
            *reinterpret_cast<uint32_t*>(sa + (row + 8) * P_SSTRIDE + col * 2) =
                *reinterpret_cast<uint32_t*>(&p23);
        }
        __syncthreads();

        float acc2[2][4];
#pragma unroll
        for (int nt = 0; nt < 2; nt++)
#pragma unroll
            for (int c = 0; c < 4; c++) acc2[nt][c] = 0.f;
#pragma unroll
        for (int k = 0; k < 256; k += 16) {
            uint32_t af[4];
            ldsm_x4(sa_u + arow * P_SSTRIDE + (k + acol8) * 2, af);
            uint32_t bf[4];
            ldsm_x4(sw2_u + brow2 * P_SSTRIDE + (k + bcol8) * 2, bf);
            mma_bf16(acc2[0], af, bf);
            mma_bf16(acc2[1], af, bf + 2);
        }

        {
            int row0 = rowbase + m_base + g;
            int row1 = row0 + 8;
            float sA = 0.f, sB = 0.f;
#pragma unroll
            for (int nt = 0; nt < 2; nt++) {
                int col = wn * 16 + nt * 8 + tig * 2;
                float b0 = fb2s[col], b1 = fb2s[col + 1];
                float w0 = fw3s[col], w1 = fw3s[col + 1];
                sA += celu3f(acc2[nt][0] + b0) * w0 + celu3f(acc2[nt][1] + b1) * w1;
                sB += celu3f(acc2[nt][2] + b0) * w0 + celu3f(acc2[nt][3] + b1) * w1;
            }
            int p = g & 1;
            float s = 0.f;
            if (row0 < ROWS_TOT) s += sA;
            if (row1 < ROWS_TOT) s += sB;
            if (p) ws1 += s; else ws0 += s;
        }
        __syncthreads();

        if (has_next) {
            *reinterpret_cast<uint4*>(sa + r0 * P_SSTRIDE + c0 * 16) = pack_bf16x8(pa0, pb0);
            *reinterpret_cast<uint4*>(sa + r1 * P_SSTRIDE + c1 * 16) = pack_bf16x8(pa1, pb1);
        }
        __syncthreads();
    }

    ws0 = wredsum(ws0);
    ws1 = wredsum(ws1);
    if (lane == 0) { red[wid * 2] = ws0; red[wid * 2 + 1] = ws1; }
    __syncthreads();
    if (tid == 0) {
        float s0 = 0.f, s1 = 0.f;
#pragma unroll
        for (int w = 0; w < 16; w++) { s0 += red[w * 2]; s1 += red[w * 2 + 1]; }
        atomicAdd(&g_w[0], s0);
        atomicAdd(&g_w[1], s1);
    }

    // ---- grid barrier (all 148 CTAs resident at 1 CTA/SM) ----
    __syncthreads();
    if (tid == 0) {
        __threadfence();
        atomicAdd(&g_bar, 1u);
        while (*((volatile unsigned int*)&g_bar) < (unsigned)MLP_GRID) {}
    }
    __syncthreads();
    __threadfence();

    // ---- beta + final blend ----
    float w0 = *((volatile float*)&g_w[0]) * (1.f / (float)NN);
    float w1 = *((volatile float*)&g_w[1]) * (1.f / (float)NN);
    float mx = fmaxf(w0, w1);
    float e0 = expf(w0 - mx), e1 = expf(w1 - mx);
    float binv = 1.f / (e0 + e1);
    float beta0 = e0 * binv, beta1 = e1 * binv;

    for (int idx = blockIdx.x * 512 + tid; idx < NN * 64; idx += MLP_GRID * 512) {
        int n = idx >> 6;
        int q = idx & 63;
        float4 z0 = reinterpret_cast<const float4*>(g_z)[(size_t)n * 128 + q];
        float4 z1 = reinterpret_cast<const float4*>(g_z)[(size_t)n * 128 + 64 + q];
        float4 o;
        o.x = beta0 * z0.x + beta1 * z1.x;
        o.y = beta0 * z0.y + beta1 * z1.y;
        o.z = beta0 * z0.z + beta1 * z1.z;
        o.w = beta0 * z0.w + beta1 * z1.w;
        reinterpret_cast<float4*>(out)[idx] = o;
    }
}

// ---------------- launch ----------------
extern "C" void kernel_launch(void* const* d_in, const int* in_sizes, int n_in,
                              void* d_out, int out_size) {
    const float* feat    = (const float*)d_in[0];
    const float* r_vec   = (const float*)d_in[1];
    const float* attn1_w = (const float*)d_in[2];
    const float* attn2   = (const float*)d_in[3];
    const float* fw1     = (const float*)d_in[4];
    const float* fb1     = (const float*)d_in[5];
    const float* fw2     = (const float*)d_in[6];
    const float* fb2     = (const float*)d_in[7];
    const float* fw3     = (const float*)d_in[8];
    const int*   inst    = (const int*)d_in[9];
    float* out = (float*)d_out;

    prep_kernel<<<PREP_GRID, 256>>>(feat, r_vec, attn1_w, fw1, fw2, inst);
    scan_kernel<<<SCAN_BLOCKS, 1024>>>();
    scatter_kernel<<<(TOT_E + 255) / 256, 256>>>(inst);
    node_fused_kernel<<<(TOT_N * 32 + 255) / 256, 256>>>(feat, attn2);

    cudaFuncSetAttribute(mlp_persist_kernel, cudaFuncAttributeMaxDynamicSharedMemorySize, P_SMEM);
    mlp_persist_kernel<<<MLP_GRID, 512, P_SMEM>>>(fb1, fb2, fw3, out);
}

// round 13
// speedup vs baseline: 1.2295x; 1.0978x over previous
#include <cuda_runtime.h>
#include <cuda_bf16.h>
#include <math.h>
#include <float.h>
#include <stdint.h>

// Problem constants (fixed by dataset)
#define NN 50000
#define HH 64
#define EE 250000
#define HEADS 4
#define TOT_E (2 * EE)             // edges across both paths
#define TOT_N (2 * NN)             // segments across both paths
#define ROWS_TOT (NN * 2)          // 100000 MLP rows (N nodes x 2 paths)
#define SCAN_BLOCKS ((TOT_N + 1023) / 1024)   // 98
#define MLP_GRID  148

// ---------------- scratch (static device memory; no allocs) ----------------
__device__ float g_fr[2][3][32][2];
__device__ float g_a1n[NN * 4];
__device__ int   g_counts[TOT_N];          // re-zeroed by scan each run
__device__ int   g_offsets[TOT_N + 1];
__device__ int   g_cursor[TOT_N];
__device__ unsigned long long g_desc[SCAN_BLOCKS];
__device__ unsigned int g_bar;
__device__ __align__(8) int2 g_einst[TOT_E];  // CSR-sorted (n1,n2) per edge
__device__ float g_z[(size_t)NN * 512];       // fp32 rows: row (2n+m) x 256
__device__ __align__(16) __nv_bfloat16 g_fw1b[256 * 256];
__device__ __align__(16) __nv_bfloat16 g_fw2b[128 * 256];
__device__ float g_w[2];

// ---------------- helpers ----------------
__device__ __forceinline__ float celu3f(float x) {
    return x > 0.f ? x : 3.f * (__expf(x * (1.f / 3.f)) - 1.f);
}
__device__ __forceinline__ float gatef(float x) {
    float e1 = __expf(x * (1.f / 3.f));
    float e3 = e1 * e1 * e1;                    // exp(x)
    float s  = __fdividef(e3, e3 + 1.f);        // sigmoid(x)
    float c1 = x > 0.f ? x : 3.f * (e1 - 1.f);  // celu3(x)
    float se = c1 * s;
    return se > 0.f ? se : 3.f * (__expf(se * (1.f / 3.f)) - 1.f);
}
__device__ __forceinline__ float wredsum(float v) {
#pragma unroll
    for (int o = 16; o; o >>= 1) v += __shfl_xor_sync(0xffffffffu, v, o);
    return v;
}
__device__ __forceinline__ uint32_t smem_to_u32(const void* p) {
    uint32_t a;
    asm("{ .reg .u64 t; cvta.to.shared.u64 t, %1; cvt.u32.u64 %0, t; }" : "=r"(a) : "l"(p));
    return a;
}
__device__ __forceinline__ void ldsm_x4(uint32_t addr, uint32_t* r) {
    asm volatile("ldmatrix.sync.aligned.m8n8.x4.shared.b16 {%0,%1,%2,%3}, [%4];"
                 : "=r"(r[0]), "=r"(r[1]), "=r"(r[2]), "=r"(r[3]) : "r"(addr));
}
__device__ __forceinline__ void mma_bf16(float* d, const uint32_t* a, const uint32_t* b) {
    asm volatile(
        "mma.sync.aligned.m16n8k16.row.col.f32.bf16.bf16.f32 "
        "{%0,%1,%2,%3}, {%4,%5,%6,%7}, {%8,%9}, {%0,%1,%2,%3};"
        : "+f"(d[0]), "+f"(d[1]), "+f"(d[2]), "+f"(d[3])
        : "r"(a[0]), "r"(a[1]), "r"(a[2]), "r"(a[3]), "r"(b[0]), "r"(b[1]));
}
__device__ __forceinline__ uint4 pack_bf16x8(float4 a, float4 b) {
    __nv_bfloat162 h0 = __floats2bfloat162_rn(a.x, a.y);
    __nv_bfloat162 h1 = __floats2bfloat162_rn(a.z, a.w);
    __nv_bfloat162 h2 = __floats2bfloat162_rn(b.x, b.y);
    __nv_bfloat162 h3 = __floats2bfloat162_rn(b.z, b.w);
    uint4 u;
    u.x = *reinterpret_cast<uint32_t*>(&h0);
    u.y = *reinterpret_cast<uint32_t*>(&h1);
    u.z = *reinterpret_cast<uint32_t*>(&h2);
    u.w = *reinterpret_cast<uint32_t*>(&h3);
    return u;
}

// ---------------- fused prep kernel (init + wconv + a1n + count) ----------------
#define PREP_WCONV_B 1
#define PREP_A1N_B   257
#define PREP_CNT_B   6507
#define PREP_GRID    8461

__global__ void prep_kernel(const float* __restrict__ feat, const float* __restrict__ r_vec,
                            const float* __restrict__ aw,
                            const float* __restrict__ fw1, const float* __restrict__ fw2,
                            const int* __restrict__ inst) {
    int b = blockIdx.x;
    int tid = threadIdx.x;
    if (b == 0) {
        if (tid < 2) g_w[tid] = 0.f;
        if (tid == 0) g_bar = 0u;
        if (tid < SCAN_BLOCKS) g_desc[tid] = 0ull;
        if (tid < 32) {
            int t = tid;
            float nre[4], nim[4];
#pragma unroll
            for (int r = 0; r < 4; r++) {
                float re = r_vec[r * 64 + t * 2];
                float im = r_vec[r * 64 + t * 2 + 1];
                float inv = rsqrtf(re * re + im * im);
                nre[r] = re * inv;
                nim[r] = im * inv;
            }
#pragma unroll
            for (int m = 0; m < 2; m++) {
                int a = 2 * m + 1, c = 2 * m;
                g_fr[m][2][t][0] = 1.f; g_fr[m][2][t][1] = 0.f;
                g_fr[m][1][t][0] = nre[a]; g_fr[m][1][t][1] = nim[a];
                g_fr[m][0][t][0] = nre[a] * nre[c] - nim[a] * nim[c];
                g_fr[m][0][t][1] = nre[a] * nim[c] + nim[a] * nre[c];
            }
        }
    } else if (b < PREP_A1N_B) {
        int i = (b - PREP_WCONV_B) * 256 + tid;
        if (i < 256 * 256) g_fw1b[i] = __float2bfloat16(fw1[i]);
        if (i < 128 * 256) g_fw2b[i] = __float2bfloat16(fw2[i]);
    } else if (b < PREP_CNT_B) {
        int gw = (b - PREP_A1N_B) * 8 + (tid >> 5);
        int lane = tid & 31;
        if (gw < NN) {
            float2 d = reinterpret_cast<const float2*>(feat)[gw * 32 + lane];
            float p[4];
#pragma unroll
            for (int h = 0; h < 4; h++) {
                float v = aw[h * 64 + 2 * lane] * d.x + aw[h * 64 + 2 * lane + 1] * d.y;
                p[h] = wredsum(v);
            }
            if (lane == 0) {
                float4 r;
                r.x = celu3f(p[0]); r.y = celu3f(p[1]); r.z = celu3f(p[2]); r.w = celu3f(p[3]);
                reinterpret_cast<float4*>(g_a1n)[gw] = r;
            }
        }
    } else {
        int idx = (b - PREP_CNT_B) * 256 + tid;
        if (idx < TOT_E) {
            int m = idx >= EE;
            int e = idx - m * EE;
            int seg = inst[(size_t)m * EE * 3 + (size_t)e * 3];
            atomicAdd(&g_counts[m * NN + seg], 1);
        }
    }
}

// ---------------- single-kernel scan (decoupled lookback) ----------------
__global__ void scan_kernel() {
    __shared__ int s[1024];
    __shared__ int exc_s;
    int t = threadIdx.x, b = blockIdx.x;
    int i = b * 1024 + t;
    int v = (i < TOT_N) ? g_counts[i] : 0;
    if (i < TOT_N) g_counts[i] = 0;
    s[t] = v;
    __syncthreads();
    for (int off = 1; off < 1024; off <<= 1) {
        int x = (t >= off) ? s[t - off] : 0;
        __syncthreads();
        s[t] += x;
        __syncthreads();
    }
    int incl = s[t];
    int total = s[1023];
    if (t == 0) {
        *((volatile unsigned long long*)&g_desc[b]) = (1ull << 32) | (unsigned)total;
        int run = 0;
        for (int p = b - 1; p >= 0; p--) {
            unsigned long long d;
            do { d = *((volatile unsigned long long*)&g_desc[p]); } while ((d >> 32) == 0ull);
            run += (int)(unsigned)d;
            if ((d >> 32) == 2ull) break;
        }
        *((volatile unsigned long long*)&g_desc[b]) = (2ull << 32) | (unsigned)(run + total);
        exc_s = run;
    }
    __syncthreads();
    int e = exc_s;
    if (i < TOT_N) {
        int o = e + incl - v;
        g_offsets[i] = o;
        g_cursor[i] = o;
    }
    if (t == 0 && b == SCAN_BLOCKS - 1) g_offsets[TOT_N] = e + total;
}

// Scatter (n1,n2) into CSR order (n0 implicit = segment id).
__global__ void scatter_kernel(const int* __restrict__ inst) {
    int idx = blockIdx.x * blockDim.x + threadIdx.x;
    if (idx >= TOT_E) return;
    int m = idx >= EE;
    int e = idx - m * EE;
    const int* ip = inst + (size_t)m * EE * 3 + (size_t)e * 3;
    int i0 = ip[0], i1 = ip[1], i2 = ip[2];
    int pos = atomicAdd(&g_cursor[m * NN + i0], 1);
    g_einst[pos] = make_int2(i1, i2);
}

// FUSED node kernel: one warp per (path, node); 2x 16-lane subgroups.
// - p=2 rotation is identity -> plain adds (no fr[2] regs).
// - p=0 rotation only needed in prologue (hoisted n0 term).
// - head-transposed reduction: quad butterfly on 4 heads, own-head select,
//   cross-quad butterfly, single celu/exp, width-4 broadcast.
__global__ __launch_bounds__(256, 5) void node_fused_kernel(
    const float* __restrict__ feat, const float* __restrict__ attn2) {
    __shared__ float s_at2[256];
    if (threadIdx.x < 256) s_at2[threadIdx.x] = attn2[threadIdx.x];
    __syncthreads();

    int gw = (blockIdx.x * blockDim.x + threadIdx.x) >> 5;
    int lane = threadIdx.x & 31;
    if (gw >= TOT_N) return;
    int m = gw >= NN;
    int n = gw - m * NN;
    int start = g_offsets[gw];
    int deg = g_offsets[gw + 1] - start;
    int sub = lane >> 4;
    int li = lane & 15;
    int tig = li & 3;

    // rotation factors: only p=1 stays live in the loop
    const float4* g_fr4 = reinterpret_cast<const float4*>(g_fr);
    float4 f1 = g_fr4[(m * 3 + 1) * 16 + li];

    // own-head a1
    float a1own = g_a1n[n * 4 + tig];

    // hoisted n0 (p=0) contribution
    float4 f0 = g_fr4[(m * 3 + 0) * 16 + li];
    float4 d0 = *reinterpret_cast<const float4*>(feat + (size_t)n * 64 + 4 * li);
    float c_re0 = d0.x * f0.x - d0.y * f0.y;
    float c_im0 = d0.x * f0.y + d0.y * f0.x;
    float c_re1 = d0.z * f0.z - d0.w * f0.w;
    float c_im1 = d0.z * f0.w + d0.w * f0.z;

    float acc[4][4];
    float den_own = 0.f;
#pragma unroll
    for (int h = 0; h < 4; h++)
#pragma unroll
        for (int j = 0; j < 4; j++) acc[h][j] = 0.f;

    int padded = (deg + 1) & ~1;
    int2 nd = (sub < padded) ? g_einst[start + ((sub < deg) ? sub : 0)] : make_int2(0, 0);
    for (int i = sub; i < padded; i += 2) {
        bool act = i < deg;
        int2 cur = nd;
        int inext = i + 2;
        if (inext < padded)
            nd = g_einst[start + ((inext < deg) ? inext : 0)];
        float mre0 = c_re0, mim0 = c_im0, mre1 = c_re1, mim1 = c_im1;
        {   // p=1 node: rotate by f1
            float4 d = *reinterpret_cast<const float4*>(feat + (size_t)cur.x * 64 + 4 * li);
            mre0 += d.x * f1.x - d.y * f1.y;
            mim0 += d.x * f1.y + d.y * f1.x;
            mre1 += d.z * f1.z - d.w * f1.w;
            mim1 += d.z * f1.w + d.w * f1.z;
        }
        {   // p=2 node: identity rotation
            float4 d = *reinterpret_cast<const float4*>(feat + (size_t)cur.y * 64 + 4 * li);
            mre0 += d.x; mim0 += d.y;
            mre1 += d.z; mim1 += d.w;
        }
        float ef[4];
        ef[0] = gatef(mre0 * (1.f / 3.f));
        ef[1] = gatef(mim0 * (1.f / 3.f));
        ef[2] = gatef(mre1 * (1.f / 3.f));
        ef[3] = gatef(mim1 * (1.f / 3.f));
        // per-head logit partials
        float ph[4];
#pragma unroll
        for (int h = 0; h < 4; h++) {
            float4 a2v = *reinterpret_cast<const float4*>(&s_at2[h * 64 + 4 * li]);
            ph[h] = a2v.x * ef[0] + a2v.y * ef[1] + a2v.z * ef[2] + a2v.w * ef[3];
            // quad butterfly (sums lanes differing in bits 0,1)
            ph[h] += __shfl_xor_sync(0xffffffffu, ph[h], 1);
            ph[h] += __shfl_xor_sync(0xffffffffu, ph[h], 2);
        }
        // own-head select + cross-quad reduction (bits 2,3)
        float v = (tig == 0) ? ph[0] : (tig == 1) ? ph[1] : (tig == 2) ? ph[2] : ph[3];
        v += __shfl_xor_sync(0xffffffffu, v, 4);
        v += __shfl_xor_sync(0xffffffffu, v, 8);
        // single-head weight
        float a = celu3f(a1own + v);
        float w = act ? __expf(a) : 0.f;
        den_own += w;
        // broadcast weights to the quad
        float wv0 = __shfl_sync(0xffffffffu, w, 0, 4);
        float wv1 = __shfl_sync(0xffffffffu, w, 1, 4);
        float wv2 = __shfl_sync(0xffffffffu, w, 2, 4);
        float wv3 = __shfl_sync(0xffffffffu, w, 3, 4);
#pragma unroll
        for (int j = 0; j < 4; j++) {
            acc[0][j] += wv0 * ef[j];
            acc[1][j] += wv1 * ef[j];
            acc[2][j] += wv2 * ef[j];
            acc[3][j] += wv3 * ef[j];
        }
    }
    // merge the two subgroups
    den_own += __shfl_xor_sync(0xffffffffu, den_own, 16);
#pragma unroll
    for (int h = 0; h < 4; h++)
#pragma unroll
        for (int j = 0; j < 4; j++)
            acc[h][j] += __shfl_xor_sync(0xffffffffu, acc[h][j], 16);

    if (sub == 0) {
        // per-head denominators from the quad
        float den[4];
        den[0] = __shfl_sync(0xffffffffu, den_own, 0, 4);
        den[1] = __shfl_sync(0xffffffffu, den_own, 1, 4);
        den[2] = __shfl_sync(0xffffffffu, den_own, 2, 4);
        den[3] = __shfl_sync(0xffffffffu, den_own, 3, 4);
        float* zr = g_z + (size_t)n * 512 + m * 256;
#pragma unroll
        for (int h = 0; h < 4; h++) {
            float inv = (deg > 0) ? __fdividef(1.f, den[h]) : 0.f;
            float z0 = celu3f(acc[h][0] * inv);
            float z1 = celu3f(acc[h][1] * inv);
            float z2 = celu3f(acc[h][2] * inv);
            float z3 = celu3f(acc[h][3] * inv);
            *reinterpret_cast<float4*>(zr + h * 64 + 4 * li) = make_float4(z0, z1, z2, z3);
        }
    }
}

// ---------------- persistent MLP + grid barrier + final blend ----------------
#define P_SSTRIDE 528
#define P_OFF_W2  135168
#define P_OFF_A   202752
#define P_OFF_FB1 219648
#define P_OFF_FB2 220672
#define P_OFF_FW3 221184
#define P_OFF_RED 221696
#define P_SMEM    221824
#define N_TILES   ((ROWS_TOT + 31) / 32)     // 3125

__global__ __launch_bounds__(512, 1) void mlp_persist_kernel(
    const float* __restrict__ fb1, const float* __restrict__ fb2,
    const float* __restrict__ fw3, float* __restrict__ out) {
    extern __shared__ char smem[];
    char* sw1 = smem;
    char* sw2 = smem + P_OFF_W2;
    char* sa  = smem + P_OFF_A;
    float* fb1s = reinterpret_cast<float*>(smem + P_OFF_FB1);
    float* fb2s = reinterpret_cast<float*>(smem + P_OFF_FB2);
    float* fw3s = reinterpret_cast<float*>(smem + P_OFF_FW3);
    float* red  = reinterpret_cast<float*>(smem + P_OFF_RED);

    uint32_t sw1_u = smem_to_u32(smem);
    uint32_t sw2_u = sw1_u + P_OFF_W2;
    uint32_t sa_u  = sw1_u + P_OFF_A;

    int tid = threadIdx.x;
    int wid = tid >> 5;
    int lane = tid & 31;
    int wm = wid >> 3;
    int wn = wid & 7;
    int m_base = wm * 16;
    int g = lane >> 2;
    int tig = lane & 3;

    for (int idx = tid; idx < 8192; idx += 512) {
        int r = idx >> 5, c = idx & 31;
        uint4 v = *reinterpret_cast<const uint4*>(g_fw1b + r * 256 + c * 8);
        *reinterpret_cast<uint4*>(sw1 + r * P_SSTRIDE + c * 16) = v;
    }
    for (int idx = tid; idx < 4096; idx += 512) {
        int r = idx >> 5, c = idx & 31;
        uint4 v = *reinterpret_cast<const uint4*>(g_fw2b + r * 256 + c * 8);
        *reinterpret_cast<uint4*>(sw2 + r * P_SSTRIDE + c * 16) = v;
    }
    for (int i = tid; i < 256; i += 512) fb1s[i] = fb1[i];
    for (int i = tid; i < 128; i += 512) { fb2s[i] = fb2[i]; fw3s[i] = fw3[i]; }

    int r0 = (tid * 2) >> 5,     c0 = (tid * 2) & 31;
    int r1 = (tid * 2 + 1) >> 5, c1 = (tid * 2 + 1) & 31;

    {
        int rowbase = blockIdx.x * 32;
        float4 a0 = make_float4(0, 0, 0, 0), b0 = a0, a1 = a0, b1 = a0;
        if (rowbase + r0 < ROWS_TOT) {
            const float4* zp = reinterpret_cast<const float4*>(g_z + (size_t)(rowbase + r0) * 256 + c0 * 8);
            a0 = zp[0]; b0 = zp[1];
        }
        if (rowbase + r1 < ROWS_TOT) {
            const float4* zp = reinterpret_cast<const float4*>(g_z + (size_t)(rowbase + r1) * 256 + c1 * 8);
            a1 = zp[0]; b1 = zp[1];
        }
        *reinterpret_cast<uint4*>(sa + r0 * P_SSTRIDE + c0 * 16) = pack_bf16x8(a0, b0);
        *reinterpret_cast<uint4*>(sa + r1 * P_SSTRIDE + c1 * 16) = pack_bf16x8(a1, b1);
    }
    __syncthreads();

    int arow  = m_base + (lane & 15);
    int acol8 = ((lane >> 4) & 1) * 8;
    int brow1 = wn * 32 + ((lane >> 4) & 1) * 8 + (lane & 7);
    int brow2 = wn * 16 + ((lane >> 4) & 1) * 8 + (lane & 7);
    int bcol8 = ((lane >> 3) & 1) * 8;

    float ws0 = 0.f, ws1 = 0.f;

    for (int t = blockIdx.x; t < N_TILES; t += MLP_GRID) {
        int rowbase = t * 32;
        int tn = t + MLP_GRID;
        bool has_next = tn < N_TILES;

        float4 pa0 = make_float4(0, 0, 0, 0), pb0 = pa0, pa1 = pa0, pb1 = pa0;
        if (has_next) {
            int nb = tn * 32;
            if (nb + r0 < ROWS_TOT) {
                const float4* zp = reinterpret_cast<const float4*>(g_z + (size_t)(nb + r0) * 256 + c0 * 8);
                pa0 = zp[0]; pb0 = zp[1];
            }
            if (nb + r1 < ROWS_TOT) {
                const float4* zp = reinterpret_cast<const float4*>(g_z + (size_t)(nb + r1) * 256 + c1 * 8);
                pa1 = zp[0]; pb1 = zp[1];
            }
        }

        float acc[4][4];
#pragma unroll
        for (int nt = 0; nt < 4; nt++)
#pragma unroll
            for (int c = 0; c < 4; c++) acc[nt][c] = 0.f;
#pragma unroll
        for (int k = 0; k < 256; k += 16) {
            uint32_t af[4];
            ldsm_x4(sa_u + arow * P_SSTRIDE + (k + acol8) * 2, af);
#pragma unroll
            for (int np = 0; np < 2; np++) {
                uint32_t bf[4];
                ldsm_x4(sw1_u + (brow1 + np * 16) * P_SSTRIDE + (k + bcol8) * 2, bf);
                mma_bf16(acc[np * 2],     af, bf);
                mma_bf16(acc[np * 2 + 1], af, bf + 2);
            }
        }
        __syncthreads();

#pragma unroll
        for (int nt = 0; nt < 4; nt++) {
            int row = m_base + g;
            int col = wn * 32 + nt * 8 + tig * 2;
            float b0 = fb1s[col], b1 = fb1s[col + 1];
            float t0 = celu3f(acc[nt][0] + b0);
            float t1 = celu3f(acc[nt][1] + b1);
            float t2 = celu3f(acc[nt][2] + b0);
            float t3 = celu3f(acc[nt][3] + b1);
            __nv_bfloat162 p01 = __floats2bfloat162_rn(t0, t1);
            __nv_bfloat162 p23 = __floats2bfloat162_rn(t2, t3);
            *reinterpret_cast<uint32_t*>(sa + row * P_SSTRIDE + col * 2) =
                *reinterpret_cast<uint32_t*>(&p01);
            *reinterpret_cast<uint32_t*>(sa + (row + 8) * P_SSTRIDE + col * 2) =
                *reinterpret_cast<uint32_t*>(&p23);
        }
        __syncthreads();

        float acc2[2][4];
#pragma unroll
        for (int nt = 0; nt < 2; nt++)
#pragma unroll
            for (int c = 0; c < 4; c++) acc2[nt][c] = 0.f;
#pragma unroll
        for (int k = 0; k < 256; k += 16) {
            uint32_t af[4];
            ldsm_x4(sa_u + arow * P_SSTRIDE + (k + acol8) * 2, af);
            uint32_t bf[4];
            ldsm_x4(sw2_u + brow2 * P_SSTRIDE + (k + bcol8) * 2, bf);
            mma_bf16(acc2[0], af, bf);
            mma_bf16(acc2[1], af, bf + 2);
        }

        {
            int row0 = rowbase + m_base + g;
            int row1 = row0 + 8;
            float sA = 0.f, sB = 0.f;
#pragma unroll
            for (int nt = 0; nt < 2; nt++) {
                int col = wn * 16 + nt * 8 + tig * 2;
                float b0 = fb2s[col], b1 = fb2s[col + 1];
                float w0 = fw3s[col], w1 = fw3s[col + 1];
                sA += celu3f(acc2[nt][0] + b0) * w0 + celu3f(acc2[nt][1] + b1) * w1;
                sB += celu3f(acc2[nt][2] + b0) * w0 + celu3f(acc2[nt][3] + b1) * w1;
            }
            int p = g & 1;
            float s = 0.f;
            if (row0 < ROWS_TOT) s += sA;
            if (row1 < ROWS_TOT) s += sB;
            if (p) ws1 += s; else ws0 += s;
        }
        __syncthreads();

        if (has_next) {
            *reinterpret_cast<uint4*>(sa + r0 * P_SSTRIDE + c0 * 16) = pack_bf16x8(pa0, pb0);
            *reinterpret_cast<uint4*>(sa + r1 * P_SSTRIDE + c1 * 16) = pack_bf16x8(pa1, pb1);
        }
        __syncthreads();
    }

    ws0 = wredsum(ws0);
    ws1 = wredsum(ws1);
    if (lane == 0) { red[wid * 2] = ws0; red[wid * 2 + 1] = ws1; }
    __syncthreads();
    if (tid == 0) {
        float s0 = 0.f, s1 = 0.f;
#pragma unroll
        for (int w = 0; w < 16; w++) { s0 += red[w * 2]; s1 += red[w * 2 + 1]; }
        atomicAdd(&g_w[0], s0);
        atomicAdd(&g_w[1], s1);
    }

    // ---- grid barrier (all 148 CTAs resident at 1 CTA/SM) ----
    __syncthreads();
    if (tid == 0) {
        __threadfence();
        atomicAdd(&g_bar, 1u);
        while (*((volatile unsigned int*)&g_bar) < (unsigned)MLP_GRID) {}
    }
    __syncthreads();
    __threadfence();

    // ---- beta + final blend ----
    float w0 = *((volatile float*)&g_w[0]) * (1.f / (float)NN);
    float w1 = *((volatile float*)&g_w[1]) * (1.f / (float)NN);
    float mx = fmaxf(w0, w1);
    float e0 = expf(w0 - mx), e1 = expf(w1 - mx);
    float binv = 1.f / (e0 + e1);
    float beta0 = e0 * binv, beta1 = e1 * binv;

    for (int idx = blockIdx.x * 512 + tid; idx < NN * 64; idx += MLP_GRID * 512) {
        int n = idx >> 6;
        int q = idx & 63;
        float4 z0 = reinterpret_cast<const float4*>(g_z)[(size_t)n * 128 + q];
        float4 z1 = reinterpret_cast<const float4*>(g_z)[(size_t)n * 128 + 64 + q];
        float4 o;
        o.x = beta0 * z0.x + beta1 * z1.x;
        o.y = beta0 * z0.y + beta1 * z1.y;
        o.z = beta0 * z0.z + beta1 * z1.z;
        o.w = beta0 * z0.w + beta1 * z1.w;
        reinterpret_cast<float4*>(out)[idx] = o;
    }
}

// ---------------- launch ----------------
extern "C" void kernel_launch(void* const* d_in, const int* in_sizes, int n_in,
                              void* d_out, int out_size) {
    const float* feat    = (const float*)d_in[0];
    const float* r_vec   = (const float*)d_in[1];
    const float* attn1_w = (const float*)d_in[2];
    const float* attn2   = (const float*)d_in[3];
    const float* fw1     = (const float*)d_in[4];
    const float* fb1     = (const float*)d_in[5];
    const float* fw2     = (const float*)d_in[6];
    const float* fb2     = (const float*)d_in[7];
    const float* fw3     = (const float*)d_in[8];
    const int*   inst    = (const int*)d_in[9];
    float* out = (float*)d_out;

    prep_kernel<<<PREP_GRID, 256>>>(feat, r_vec, attn1_w, fw1, fw2, inst);
    scan_kernel<<<SCAN_BLOCKS, 1024>>>();
    scatter_kernel<<<(TOT_E + 255) / 256, 256>>>(inst);
    node_fused_kernel<<<(TOT_N * 32 + 255) / 256, 256>>>(feat, attn2);

    cudaFuncSetAttribute(mlp_persist_kernel, cudaFuncAttributeMaxDynamicSharedMemorySize, P_SMEM);
    mlp_persist_kernel<<<MLP_GRID, 512, P_SMEM>>>(fb1, fb2, fw3, out);
}

// round 15
// speedup vs baseline: 1.2448x; 1.0125x over previous
#include <cuda_runtime.h>
#include <cuda_bf16.h>
#include <math.h>
#include <float.h>
#include <stdint.h>

// Problem constants (fixed by dataset)
#define NN 50000
#define HH 64
#define EE 250000
#define HEADS 4
#define TOT_E (2 * EE)             // edges across both paths
#define TOT_N (2 * NN)             // segments across both paths
#define ROWS_TOT (NN * 2)          // 100000 MLP rows (N nodes x 2 paths)
#define SCAN_BLOCKS ((TOT_N + 1023) / 1024)   // 98
#define MLP_GRID  148

// ---------------- scratch (static device memory; no allocs) ----------------
__device__ float g_fr[2][3][32][2];
__device__ float g_a1n[NN * 4];
__device__ int   g_counts[TOT_N];          // re-zeroed by scan each run
__device__ int   g_offsets[TOT_N + 1];
__device__ int   g_cursor[TOT_N];
__device__ unsigned long long g_desc[SCAN_BLOCKS];
__device__ unsigned int g_bar;
__device__ __align__(8) int2 g_einst[TOT_E];  // CSR-sorted (n1,n2) per edge
__device__ float g_z[(size_t)NN * 512];       // fp32 rows: row (2n+m) x 256
__device__ __align__(16) __nv_bfloat16 g_fw1b[256 * 256];
__device__ __align__(16) __nv_bfloat16 g_fw2b[128 * 256];
__device__ float g_w[2];

// ---------------- helpers ----------------
__device__ __forceinline__ float celu3f(float x) {
    return x > 0.f ? x : 3.f * (__expf(x * (1.f / 3.f)) - 1.f);
}
__device__ __forceinline__ float gatef(float x) {
    float e1 = __expf(x * (1.f / 3.f));
    float e3 = e1 * e1 * e1;                    // exp(x)
    float s  = __fdividef(e3, e3 + 1.f);        // sigmoid(x)
    float c1 = x > 0.f ? x : 3.f * (e1 - 1.f);  // celu3(x)
    float se = c1 * s;
    return se > 0.f ? se : 3.f * (__expf(se * (1.f / 3.f)) - 1.f);
}
__device__ __forceinline__ float wredsum(float v) {
#pragma unroll
    for (int o = 16; o; o >>= 1) v += __shfl_xor_sync(0xffffffffu, v, o);
    return v;
}
__device__ __forceinline__ uint32_t smem_to_u32(const void* p) {
    uint32_t a;
    asm("{ .reg .u64 t; cvta.to.shared.u64 t, %1; cvt.u32.u64 %0, t; }" : "=r"(a) : "l"(p));
    return a;
}
__device__ __forceinline__ void ldsm_x4(uint32_t addr, uint32_t* r) {
    asm volatile("ldmatrix.sync.aligned.m8n8.x4.shared.b16 {%0,%1,%2,%3}, [%4];"
                 : "=r"(r[0]), "=r"(r[1]), "=r"(r[2]), "=r"(r[3]) : "r"(addr));
}
__device__ __forceinline__ void mma_bf16(float* d, const uint32_t* a, const uint32_t* b) {
    asm volatile(
        "mma.sync.aligned.m16n8k16.row.col.f32.bf16.bf16.f32 "
        "{%0,%1,%2,%3}, {%4,%5,%6,%7}, {%8,%9}, {%0,%1,%2,%3};"
        : "+f"(d[0]), "+f"(d[1]), "+f"(d[2]), "+f"(d[3])
        : "r"(a[0]), "r"(a[1]), "r"(a[2]), "r"(a[3]), "r"(b[0]), "r"(b[1]));
}
__device__ __forceinline__ uint4 pack_bf16x8(float4 a, float4 b) {
    __nv_bfloat162 h0 = __floats2bfloat162_rn(a.x, a.y);
    __nv_bfloat162 h1 = __floats2bfloat162_rn(a.z, a.w);
    __nv_bfloat162 h2 = __floats2bfloat162_rn(b.x, b.y);
    __nv_bfloat162 h3 = __floats2bfloat162_rn(b.z, b.w);
    uint4 u;
    u.x = *reinterpret_cast<uint32_t*>(&h0);
    u.y = *reinterpret_cast<uint32_t*>(&h1);
    u.z = *reinterpret_cast<uint32_t*>(&h2);
    u.w = *reinterpret_cast<uint32_t*>(&h3);
    return u;
}

// ---------------- fused prep kernel (init + wconv + a1n + count) ----------------
#define PREP_WCONV_B 1
#define PREP_A1N_B   257
#define PREP_CNT_B   6507
#define PREP_GRID    8461

__global__ void prep_kernel(const float* __restrict__ feat, const float* __restrict__ r_vec,
                            const float* __restrict__ aw,
                            const float* __restrict__ fw1, const float* __restrict__ fw2,
                            const int* __restrict__ inst) {
    int b = blockIdx.x;
    int tid = threadIdx.x;
    if (b == 0) {
        if (tid < 2) g_w[tid] = 0.f;
        if (tid == 0) g_bar = 0u;
        if (tid < SCAN_BLOCKS) g_desc[tid] = 0ull;
        if (tid < 32) {
            int t = tid;
            float nre[4], nim[4];
#pragma unroll
            for (int r = 0; r < 4; r++) {
                float re = r_vec[r * 64 + t * 2];
                float im = r_vec[r * 64 + t * 2 + 1];
                float inv = rsqrtf(re * re + im * im);
                nre[r] = re * inv;
                nim[r] = im * inv;
            }
#pragma unroll
            for (int m = 0; m < 2; m++) {
                int a = 2 * m + 1, c = 2 * m;
                g_fr[m][2][t][0] = 1.f; g_fr[m][2][t][1] = 0.f;
                g_fr[m][1][t][0] = nre[a]; g_fr[m][1][t][1] = nim[a];
                g_fr[m][0][t][0] = nre[a] * nre[c] - nim[a] * nim[c];
                g_fr[m][0][t][1] = nre[a] * nim[c] + nim[a] * nre[c];
            }
        }
    } else if (b < PREP_A1N_B) {
        int i = (b - PREP_WCONV_B) * 256 + tid;
        if (i < 256 * 256) g_fw1b[i] = __float2bfloat16(fw1[i]);
        if (i < 128 * 256) g_fw2b[i] = __float2bfloat16(fw2[i]);
    } else if (b < PREP_CNT_B) {
        int gw = (b - PREP_A1N_B) * 8 + (tid >> 5);
        int lane = tid & 31;
        if (gw < NN) {
            float2 d = reinterpret_cast<const float2*>(feat)[gw * 32 + lane];
            float p[4];
#pragma unroll
            for (int h = 0; h < 4; h++) {
                float v = aw[h * 64 + 2 * lane] * d.x + aw[h * 64 + 2 * lane + 1] * d.y;
                p[h] = wredsum(v);
            }
            if (lane == 0) {
                float4 r;
                r.x = celu3f(p[0]); r.y = celu3f(p[1]); r.z = celu3f(p[2]); r.w = celu3f(p[3]);
                reinterpret_cast<float4*>(g_a1n)[gw] = r;
            }
        }
    } else {
        int idx = (b - PREP_CNT_B) * 256 + tid;
        if (idx < TOT_E) {
            int m = idx >= EE;
            int e = idx - m * EE;
            int seg = inst[(size_t)m * EE * 3 + (size_t)e * 3];
            atomicAdd(&g_counts[m * NN + seg], 1);
        }
    }
}

// ---------------- single-kernel scan (decoupled lookback) ----------------
__global__ void scan_kernel() {
    __shared__ int s[1024];
    __shared__ int exc_s;
    int t = threadIdx.x, b = blockIdx.x;
    int i = b * 1024 + t;
    int v = (i < TOT_N) ? g_counts[i] : 0;
    if (i < TOT_N) g_counts[i] = 0;
    s[t] = v;
    __syncthreads();
    for (int off = 1; off < 1024; off <<= 1) {
        int x = (t >= off) ? s[t - off] : 0;
        __syncthreads();
        s[t] += x;
        __syncthreads();
    }
    int incl = s[t];
    int total = s[1023];
    if (t == 0) {
        *((volatile unsigned long long*)&g_desc[b]) = (1ull << 32) | (unsigned)total;
        int run = 0;
        for (int p = b - 1; p >= 0; p--) {
            unsigned long long d;
            do { d = *((volatile unsigned long long*)&g_desc[p]); } while ((d >> 32) == 0ull);
            run += (int)(unsigned)d;
            if ((d >> 32) == 2ull) break;
        }
        *((volatile unsigned long long*)&g_desc[b]) = (2ull << 32) | (unsigned)(run + total);
        exc_s = run;
    }
    __syncthreads();
    int e = exc_s;
    if (i < TOT_N) {
        int o = e + incl - v;
        g_offsets[i] = o;
        g_cursor[i] = o;
    }
    if (t == 0 && b == SCAN_BLOCKS - 1) g_offsets[TOT_N] = e + total;
}

// Scatter (n1,n2) into CSR order (n0 implicit = segment id).
__global__ void scatter_kernel(const int* __restrict__ inst) {
    int idx = blockIdx.x * blockDim.x + threadIdx.x;
    if (idx >= TOT_E) return;
    int m = idx >= EE;
    int e = idx - m * EE;
    const int* ip = inst + (size_t)m * EE * 3 + (size_t)e * 3;
    int i0 = ip[0], i1 = ip[1], i2 = ip[2];
    int pos = atomicAdd(&g_cursor[m * NN + i0], 1);
    g_einst[pos] = make_int2(i1, i2);
}

// FUSED node kernel: one warp per NODE, both paths (m=0,1) processed
// sequentially (amortizes d0 gather, a1n load, setup; halves grid/tail).
// NOTE: all __shfl_sync ops execute in full-warp-converged regions; the
// den broadcast is hoisted OUT of the sub==0 branch (the divergent full-mask
// shfl was the R14 illegal-instruction trap).
__global__ __launch_bounds__(256, 5) void node_fused_kernel(
    const float* __restrict__ feat, const float* __restrict__ attn2) {
    __shared__ float s_at2[256];
    if (threadIdx.x < 256) s_at2[threadIdx.x] = attn2[threadIdx.x];
    __syncthreads();

    int n = (blockIdx.x * blockDim.x + threadIdx.x) >> 5;
    int lane = threadIdx.x & 31;
    if (n >= NN) return;
    int sub = lane >> 4;
    int li = lane & 15;
    int tig = li & 3;

    const float4* g_fr4 = reinterpret_cast<const float4*>(g_fr);
    // shared across both paths
    float a1own = g_a1n[n * 4 + tig];
    float4 d0 = *reinterpret_cast<const float4*>(feat + (size_t)n * 64 + 4 * li);

#pragma unroll 1
    for (int m = 0; m < 2; m++) {
        int seg = m * NN + n;
        int start = g_offsets[seg];
        int deg = g_offsets[seg + 1] - start;

        float4 f1 = g_fr4[(m * 3 + 1) * 16 + li];
        float4 f0 = g_fr4[(m * 3 + 0) * 16 + li];
        float c_re0 = d0.x * f0.x - d0.y * f0.y;
        float c_im0 = d0.x * f0.y + d0.y * f0.x;
        float c_re1 = d0.z * f0.z - d0.w * f0.w;
        float c_im1 = d0.z * f0.w + d0.w * f0.z;

        float acc[4][4];
        float den_own = 0.f;
#pragma unroll
        for (int h = 0; h < 4; h++)
#pragma unroll
            for (int j = 0; j < 4; j++) acc[h][j] = 0.f;

        int padded = (deg + 1) & ~1;
        int2 nd = (sub < padded) ? g_einst[start + ((sub < deg) ? sub : 0)] : make_int2(0, 0);
        for (int i = sub; i < padded; i += 2) {
            bool act = i < deg;
            int2 cur = nd;
            int inext = i + 2;
            if (inext < padded)
                nd = g_einst[start + ((inext < deg) ? inext : 0)];
            float mre0 = c_re0, mim0 = c_im0, mre1 = c_re1, mim1 = c_im1;
            {   // p=1 node: rotate by f1
                float4 d = *reinterpret_cast<const float4*>(feat + (size_t)cur.x * 64 + 4 * li);
                mre0 += d.x * f1.x - d.y * f1.y;
                mim0 += d.x * f1.y + d.y * f1.x;
                mre1 += d.z * f1.z - d.w * f1.w;
                mim1 += d.z * f1.w + d.w * f1.z;
            }
            {   // p=2 node: identity rotation
                float4 d = *reinterpret_cast<const float4*>(feat + (size_t)cur.y * 64 + 4 * li);
                mre0 += d.x; mim0 += d.y;
                mre1 += d.z; mim1 += d.w;
            }
            float ef[4];
            ef[0] = gatef(mre0 * (1.f / 3.f));
            ef[1] = gatef(mim0 * (1.f / 3.f));
            ef[2] = gatef(mre1 * (1.f / 3.f));
            ef[3] = gatef(mim1 * (1.f / 3.f));
            float ph[4];
#pragma unroll
            for (int h = 0; h < 4; h++) {
                float4 a2v = *reinterpret_cast<const float4*>(&s_at2[h * 64 + 4 * li]);
                ph[h] = a2v.x * ef[0] + a2v.y * ef[1] + a2v.z * ef[2] + a2v.w * ef[3];
                ph[h] += __shfl_xor_sync(0xffffffffu, ph[h], 1);
                ph[h] += __shfl_xor_sync(0xffffffffu, ph[h], 2);
            }
            float v = (tig == 0) ? ph[0] : (tig == 1) ? ph[1] : (tig == 2) ? ph[2] : ph[3];
            v += __shfl_xor_sync(0xffffffffu, v, 4);
            v += __shfl_xor_sync(0xffffffffu, v, 8);
            float a = celu3f(a1own + v);
            float w = act ? __expf(a) : 0.f;
            den_own += w;
            float wv0 = __shfl_sync(0xffffffffu, w, 0, 4);
            float wv1 = __shfl_sync(0xffffffffu, w, 1, 4);
            float wv2 = __shfl_sync(0xffffffffu, w, 2, 4);
            float wv3 = __shfl_sync(0xffffffffu, w, 3, 4);
#pragma unroll
            for (int j = 0; j < 4; j++) {
                acc[0][j] += wv0 * ef[j];
                acc[1][j] += wv1 * ef[j];
                acc[2][j] += wv2 * ef[j];
                acc[3][j] += wv3 * ef[j];
            }
        }
        // merge the two subgroups (full warp converged)
        den_own += __shfl_xor_sync(0xffffffffu, den_own, 16);
#pragma unroll
        for (int h = 0; h < 4; h++)
#pragma unroll
            for (int j = 0; j < 4; j++)
                acc[h][j] += __shfl_xor_sync(0xffffffffu, acc[h][j], 16);

        // per-head denominators: broadcast while the FULL warp is converged
        float den0 = __shfl_sync(0xffffffffu, den_own, 0, 4);
        float den1 = __shfl_sync(0xffffffffu, den_own, 1, 4);
        float den2 = __shfl_sync(0xffffffffu, den_own, 2, 4);
        float den3 = __shfl_sync(0xffffffffu, den_own, 3, 4);

        if (sub == 0) {
            float den[4] = {den0, den1, den2, den3};
            float* zr = g_z + (size_t)n * 512 + m * 256;
#pragma unroll
            for (int h = 0; h < 4; h++) {
                float inv = (deg > 0) ? __fdividef(1.f, den[h]) : 0.f;
                float z0 = celu3f(acc[h][0] * inv);
                float z1 = celu3f(acc[h][1] * inv);
                float z2 = celu3f(acc[h][2] * inv);
                float z3 = celu3f(acc[h][3] * inv);
                *reinterpret_cast<float4*>(zr + h * 64 + 4 * li) = make_float4(z0, z1, z2, z3);
            }
        }
    }
}

// ---------------- persistent MLP + grid barrier + final blend ----------------
#define P_SSTRIDE 528
#define P_OFF_W2  135168
#define P_OFF_A   202752
#define P_OFF_FB1 219648
#define P_OFF_FB2 220672
#define P_OFF_FW3 221184
#define P_OFF_RED 221696
#define P_SMEM    221824
#define N_TILES   ((ROWS_TOT + 31) / 32)     // 3125

__global__ __launch_bounds__(512, 1) void mlp_persist_kernel(
    const float* __restrict__ fb1, const float* __restrict__ fb2,
    const float* __restrict__ fw3, float* __restrict__ out) {
    extern __shared__ char smem[];
    char* sw1 = smem;
    char* sw2 = smem + P_OFF_W2;
    char* sa  = smem + P_OFF_A;
    float* fb1s = reinterpret_cast<float*>(smem + P_OFF_FB1);
    float* fb2s = reinterpret_cast<float*>(smem + P_OFF_FB2);
    float* fw3s = reinterpret_cast<float*>(smem + P_OFF_FW3);
    float* red  = reinterpret_cast<float*>(smem + P_OFF_RED);

    uint32_t sw1_u = smem_to_u32(smem);
    uint32_t sw2_u = sw1_u + P_OFF_W2;
    uint32_t sa_u  = sw1_u + P_OFF_A;

    int tid = threadIdx.x;
    int wid = tid >> 5;
    int lane = tid & 31;
    int wm = wid >> 3;
    int wn = wid & 7;
    int m_base = wm * 16;
    int g = lane >> 2;
    int tig = lane & 3;

    for (int idx = tid; idx < 8192; idx += 512) {
        int r = idx >> 5, c = idx & 31;
        uint4 v = *reinterpret_cast<const uint4*>(g_fw1b + r * 256 + c * 8);
        *reinterpret_cast<uint4*>(sw1 + r * P_SSTRIDE + c * 16) = v;
    }
    for (int idx = tid; idx < 4096; idx += 512) {
        int r = idx >> 5, c = idx & 31;
        uint4 v = *reinterpret_cast<const uint4*>(g_fw2b + r * 256 + c * 8);
        *reinterpret_cast<uint4*>(sw2 + r * P_SSTRIDE + c * 16) = v;
    }
    for (int i = tid; i < 256; i += 512) fb1s[i] = fb1[i];
    for (int i = tid; i < 128; i += 512) { fb2s[i] = fb2[i]; fw3s[i] = fw3[i]; }

    int r0 = (tid * 2) >> 5,     c0 = (tid * 2) & 31;
    int r1 = (tid * 2 + 1) >> 5, c1 = (tid * 2 + 1) & 31;

    {
        int rowbase = blockIdx.x * 32;
        float4 a0 = make_float4(0, 0, 0, 0), b0 = a0, a1 = a0, b1 = a0;
        if (rowbase + r0 < ROWS_TOT) {
            const float4* zp = reinterpret_cast<const float4*>(g_z + (size_t)(rowbase + r0) * 256 + c0 * 8);
            a0 = zp[0]; b0 = zp[1];
        }
        if (rowbase + r1 < ROWS_TOT) {
            const float4* zp = reinterpret_cast<const float4*>(g_z + (size_t)(rowbase + r1) * 256 + c1 * 8);
            a1 = zp[0]; b1 = zp[1];
        }
        *reinterpret_cast<uint4*>(sa + r0 * P_SSTRIDE + c0 * 16) = pack_bf16x8(a0, b0);
        *reinterpret_cast<uint4*>(sa + r1 * P_SSTRIDE + c1 * 16) = pack_bf16x8(a1, b1);
    }
    __syncthreads();

    int arow  = m_base + (lane & 15);
    int acol8 = ((lane >> 4) & 1) * 8;
    int brow1 = wn * 32 + ((lane >> 4) & 1) * 8 + (lane & 7);
    int brow2 = wn * 16 + ((lane >> 4) & 1) * 8 + (lane & 7);
    int bcol8 = ((lane >> 3) & 1) * 8;

    float ws0 = 0.f, ws1 = 0.f;

    for (int t = blockIdx.x; t < N_TILES; t += MLP_GRID) {
        int rowbase = t * 32;
        int tn = t + MLP_GRID;
        bool has_next = tn < N_TILES;

        float4 pa0 = make_float4(0, 0, 0, 0), pb0 = pa0, pa1 = pa0, pb1 = pa0;
        if (has_next) {
            int nb = tn * 32;
            if (nb + r0 < ROWS_TOT) {
                const float4* zp = reinterpret_cast<const float4*>(g_z + (size_t)(nb + r0) * 256 + c0 * 8);
                pa0 = zp[0]; pb0 = zp[1];
            }
            if (nb + r1 < ROWS_TOT) {
                const float4* zp = reinterpret_cast<const float4*>(g_z + (size_t)(nb + r1) * 256 + c1 * 8);
                pa1 = zp[0]; pb1 = zp[1];
            }
        }

        float acc[4][4];
#pragma unroll
        for (int nt = 0; nt < 4; nt++)
#pragma unroll
            for (int c = 0; c < 4; c++) acc[nt][c] = 0.f;
#pragma unroll
        for (int k = 0; k < 256; k += 16) {
            uint32_t af[4];
            ldsm_x4(sa_u + arow * P_SSTRIDE + (k + acol8) * 2, af);
#pragma unroll
            for (int np = 0; np < 2; np++) {
                uint32_t bf[4];
                ldsm_x4(sw1_u + (brow1 + np * 16) * P_SSTRIDE + (k + bcol8) * 2, bf);
                mma_bf16(acc[np * 2],     af, bf);
                mma_bf16(acc[np * 2 + 1], af, bf + 2);
            }
        }
        __syncthreads();

#pragma unroll
        for (int nt = 0; nt < 4; nt++) {
            int row = m_base + g;
            int col = wn * 32 + nt * 8 + tig * 2;
            float b0 = fb1s[col], b1 = fb1s[col + 1];
            float t0 = celu3f(acc[nt][0] + b0);
            float t1 = celu3f(acc[nt][1] + b1);
            float t2 = celu3f(acc[nt][2] + b0);
            float t3 = celu3f(acc[nt][3] + b1);
            __nv_bfloat162 p01 = __floats2bfloat162_rn(t0, t1);
            __nv_bfloat162 p23 = __floats2bfloat162_rn(t2, t3);
            *reinterpret_cast<uint32_t*>(sa + row * P_SSTRIDE + col * 2) =
                *reinterpret_cast<uint32_t*>(&p01);
            *reinterpret_cast<uint32_t*>(sa + (row + 8) * P_SSTRIDE + col * 2) =
                *reinterpret_cast<uint32_t*>(&p23);
        }
        __syncthreads();

        float acc2[2][4];
#pragma unroll
        for (int nt = 0; nt < 2; nt++)
#pragma unroll
            for (int c = 0; c < 4; c++) acc2[nt][c] = 0.f;
#pragma unroll
        for (int k = 0; k < 256; k += 16) {
            uint32_t af[4];
            ldsm_x4(sa_u + arow * P_SSTRIDE + (k + acol8) * 2, af);
            uint32_t bf[4];
            ldsm_x4(sw2_u + brow2 * P_SSTRIDE + (k + bcol8) * 2, bf);
            mma_bf16(acc2[0], af, bf);
            mma_bf16(acc2[1], af, bf + 2);
        }

        {
            int row0 = rowbase + m_base + g;
            int row1 = row0 + 8;
            float sA = 0.f, sB = 0.f;
#pragma unroll
            for (int nt = 0; nt < 2; nt++) {
                int col = wn * 16 + nt * 8 + tig * 2;
                float b0 = fb2s[col], b1 = fb2s[col + 1];
                float w0 = fw3s[col], w1 = fw3s[col + 1];
                sA += celu3f(acc2[nt][0] + b0) * w0 + celu3f(acc2[nt][1] + b1) * w1;
                sB += celu3f(acc2[nt][2] + b0) * w0 + celu3f(acc2[nt][3] + b1) * w1;
            }
            int p = g & 1;
            float s = 0.f;
            if (row0 < ROWS_TOT) s += sA;
            if (row1 < ROWS_TOT) s += sB;
            if (p) ws1 += s; else ws0 += s;
        }
        __syncthreads();

        if (has_next) {
            *reinterpret_cast<uint4*>(sa + r0 * P_SSTRIDE + c0 * 16) = pack_bf16x8(pa0, pb0);
            *reinterpret_cast<uint4*>(sa + r1 * P_SSTRIDE + c1 * 16) = pack_bf16x8(pa1, pb1);
        }
        __syncthreads();
    }

    ws0 = wredsum(ws0);
    ws1 = wredsum(ws1);
    if (lane == 0) { red[wid * 2] = ws0; red[wid * 2 + 1] = ws1; }
    __syncthreads();
    if (tid == 0) {
        float s0 = 0.f, s1 = 0.f;
#pragma unroll
        for (int w = 0; w < 16; w++) { s0 += red[w * 2]; s1 += red[w * 2 + 1]; }
        atomicAdd(&g_w[0], s0);
        atomicAdd(&g_w[1], s1);
    }

    // ---- grid barrier (all 148 CTAs resident at 1 CTA/SM) ----
    __syncthreads();
    if (tid == 0) {
        __threadfence();
        atomicAdd(&g_bar, 1u);
        while (*((volatile unsigned int*)&g_bar) < (unsigned)MLP_GRID) {}
    }
    __syncthreads();
    __threadfence();

    // ---- beta + final blend ----
    float w0 = *((volatile float*)&g_w[0]) * (1.f / (float)NN);
    float w1 = *((volatile float*)&g_w[1]) * (1.f / (float)NN);
    float mx = fmaxf(w0, w1);
    float e0 = expf(w0 - mx), e1 = expf(w1 - mx);
    float binv = 1.f / (e0 + e1);
    float beta0 = e0 * binv, beta1 = e1 * binv;

    for (int idx = blockIdx.x * 512 + tid; idx < NN * 64; idx += MLP_GRID * 512) {
        int n = idx >> 6;
        int q = idx & 63;
        float4 z0 = reinterpret_cast<const float4*>(g_z)[(size_t)n * 128 + q];
        float4 z1 = reinterpret_cast<const float4*>(g_z)[(size_t)n * 128 + 64 + q];
        float4 o;
        o.x = beta0 * z0.x + beta1 * z1.x;
        o.y = beta0 * z0.y + beta1 * z1.y;
        o.z = beta0 * z0.z + beta1 * z1.z;
        o.w = beta0 * z0.w + beta1 * z1.w;
        reinterpret_cast<float4*>(out)[idx] = o;
    }
}

// ---------------- launch ----------------
extern "C" void kernel_launch(void* const* d_in, const int* in_sizes, int n_in,
                              void* d_out, int out_size) {
    const float* feat    = (const float*)d_in[0];
    const float* r_vec   = (const float*)d_in[1];
    const float* attn1_w = (const float*)d_in[2];
    const float* attn2   = (const float*)d_in[3];
    const float* fw1     = (const float*)d_in[4];
    const float* fb1     = (const float*)d_in[5];
    const float* fw2     = (const float*)d_in[6];
    const float* fb2     = (const float*)d_in[7];
    const float* fw3     = (const float*)d_in[8];
    const int*   inst    = (const int*)d_in[9];
    float* out = (float*)d_out;

    prep_kernel<<<PREP_GRID, 256>>>(feat, r_vec, attn1_w, fw1, fw2, inst);
    scan_kernel<<<SCAN_BLOCKS, 1024>>>();
    scatter_kernel<<<(TOT_E + 255) / 256, 256>>>(inst);
    node_fused_kernel<<<(NN * 32 + 255) / 256, 256>>>(feat, attn2);

    cudaFuncSetAttribute(mlp_persist_kernel, cudaFuncAttributeMaxDynamicSharedMemorySize, P_SMEM);
    mlp_persist_kernel<<<MLP_GRID, 512, P_SMEM>>>(fb1, fb2, fw3, out);
}

// round 16
// speedup vs baseline: 1.2533x; 1.0068x over previous
#include <cuda_runtime.h>
#include <cuda_bf16.h>
#include <math.h>
#include <float.h>
#include <stdint.h>

// Problem constants (fixed by dataset)
#define NN 50000
#define HH 64
#define EE 250000
#define HEADS 4
#define TOT_E (2 * EE)             // edges across both paths
#define TOT_N (2 * NN)             // segments across both paths
#define ROWS_TOT (NN * 2)          // 100000 MLP rows (N nodes x 2 paths)
#define SCAN_BLOCKS ((TOT_N + 1023) / 1024)   // 98
#define MLP_GRID  148

// ---------------- scratch (static device memory; no allocs) ----------------
__device__ float g_fr[2][3][32][2];
__device__ float g_a1n[NN * 4];
__device__ int   g_counts[TOT_N];          // re-zeroed by scan each run
__device__ int   g_offsets[TOT_N + 1];
__device__ int   g_cursor[TOT_N];
__device__ unsigned long long g_desc[SCAN_BLOCKS];
__device__ unsigned int g_bar;             // MLP grid barrier
__device__ unsigned int g_bar2;            // scan/scatter grid barrier
__device__ __align__(8) int2 g_einst[TOT_E];  // CSR-sorted (n1,n2) per edge
__device__ float g_z[(size_t)NN * 512];       // fp32 rows: row (2n+m) x 256
__device__ __align__(16) __nv_bfloat16 g_fw1b[256 * 256];
__device__ __align__(16) __nv_bfloat16 g_fw2b[128 * 256];
__device__ float g_w[2];

// ---------------- helpers ----------------
__device__ __forceinline__ float celu3f(float x) {
    return x > 0.f ? x : 3.f * (__expf(x * (1.f / 3.f)) - 1.f);
}
__device__ __forceinline__ float gatef(float x) {
    float e1 = __expf(x * (1.f / 3.f));
    float e3 = e1 * e1 * e1;                    // exp(x)
    float s  = __fdividef(e3, e3 + 1.f);        // sigmoid(x)
    float c1 = x > 0.f ? x : 3.f * (e1 - 1.f);  // celu3(x)
    float se = c1 * s;
    return se > 0.f ? se : 3.f * (__expf(se * (1.f / 3.f)) - 1.f);
}
__device__ __forceinline__ float wredsum(float v) {
#pragma unroll
    for (int o = 16; o; o >>= 1) v += __shfl_xor_sync(0xffffffffu, v, o);
    return v;
}
__device__ __forceinline__ uint32_t smem_to_u32(const void* p) {
    uint32_t a;
    asm("{ .reg .u64 t; cvta.to.shared.u64 t, %1; cvt.u32.u64 %0, t; }" : "=r"(a) : "l"(p));
    return a;
}
__device__ __forceinline__ void ldsm_x4(uint32_t addr, uint32_t* r) {
    asm volatile("ldmatrix.sync.aligned.m8n8.x4.shared.b16 {%0,%1,%2,%3}, [%4];"
                 : "=r"(r[0]), "=r"(r[1]), "=r"(r[2]), "=r"(r[3]) : "r"(addr));
}
__device__ __forceinline__ void mma_bf16(float* d, const uint32_t* a, const uint32_t* b) {
    asm volatile(
        "mma.sync.aligned.m16n8k16.row.col.f32.bf16.bf16.f32 "
        "{%0,%1,%2,%3}, {%4,%5,%6,%7}, {%8,%9}, {%0,%1,%2,%3};"
        : "+f"(d[0]), "+f"(d[1]), "+f"(d[2]), "+f"(d[3])
        : "r"(a[0]), "r"(a[1]), "r"(a[2]), "r"(a[3]), "r"(b[0]), "r"(b[1]));
}
__device__ __forceinline__ uint4 pack_bf16x8(float4 a, float4 b) {
    __nv_bfloat162 h0 = __floats2bfloat162_rn(a.x, a.y);
    __nv_bfloat162 h1 = __floats2bfloat162_rn(a.z, a.w);
    __nv_bfloat162 h2 = __floats2bfloat162_rn(b.x, b.y);
    __nv_bfloat162 h3 = __floats2bfloat162_rn(b.z, b.w);
    uint4 u;
    u.x = *reinterpret_cast<uint32_t*>(&h0);
    u.y = *reinterpret_cast<uint32_t*>(&h1);
    u.z = *reinterpret_cast<uint32_t*>(&h2);
    u.w = *reinterpret_cast<uint32_t*>(&h3);
    return u;
}

// ---------------- fused prep kernel (init + wconv + a1n + count) ----------------
#define PREP_WCONV_B 1
#define PREP_A1N_B   257
#define PREP_CNT_B   6507
#define PREP_GRID    8461

__global__ void prep_kernel(const float* __restrict__ feat, const float* __restrict__ r_vec,
                            const float* __restrict__ aw,
                            const float* __restrict__ fw1, const float* __restrict__ fw2,
                            const int* __restrict__ inst) {
    int b = blockIdx.x;
    int tid = threadIdx.x;
    if (b == 0) {
        if (tid < 2) g_w[tid] = 0.f;
        if (tid == 0) { g_bar = 0u; g_bar2 = 0u; }
        if (tid < SCAN_BLOCKS) g_desc[tid] = 0ull;
        if (tid < 32) {
            int t = tid;
            float nre[4], nim[4];
#pragma unroll
            for (int r = 0; r < 4; r++) {
                float re = r_vec[r * 64 + t * 2];
                float im = r_vec[r * 64 + t * 2 + 1];
                float inv = rsqrtf(re * re + im * im);
                nre[r] = re * inv;
                nim[r] = im * inv;
            }
#pragma unroll
            for (int m = 0; m < 2; m++) {
                int a = 2 * m + 1, c = 2 * m;
                g_fr[m][2][t][0] = 1.f; g_fr[m][2][t][1] = 0.f;
                g_fr[m][1][t][0] = nre[a]; g_fr[m][1][t][1] = nim[a];
                g_fr[m][0][t][0] = nre[a] * nre[c] - nim[a] * nim[c];
                g_fr[m][0][t][1] = nre[a] * nim[c] + nim[a] * nre[c];
            }
        }
    } else if (b < PREP_A1N_B) {
        int i = (b - PREP_WCONV_B) * 256 + tid;
        if (i < 256 * 256) g_fw1b[i] = __float2bfloat16(fw1[i]);
        if (i < 128 * 256) g_fw2b[i] = __float2bfloat16(fw2[i]);
    } else if (b < PREP_CNT_B) {
        int gw = (b - PREP_A1N_B) * 8 + (tid >> 5);
        int lane = tid & 31;
        if (gw < NN) {
            float2 d = reinterpret_cast<const float2*>(feat)[gw * 32 + lane];
            float p[4];
#pragma unroll
            for (int h = 0; h < 4; h++) {
                float v = aw[h * 64 + 2 * lane] * d.x + aw[h * 64 + 2 * lane + 1] * d.y;
                p[h] = wredsum(v);
            }
            if (lane == 0) {
                float4 r;
                r.x = celu3f(p[0]); r.y = celu3f(p[1]); r.z = celu3f(p[2]); r.w = celu3f(p[3]);
                reinterpret_cast<float4*>(g_a1n)[gw] = r;
            }
        }
    } else {
        int idx = (b - PREP_CNT_B) * 256 + tid;
        if (idx < TOT_E) {
            int m = idx >= EE;
            int e = idx - m * EE;
            int seg = inst[(size_t)m * EE * 3 + (size_t)e * 3];
            atomicAdd(&g_counts[m * NN + seg], 1);
        }
    }
}

// ---------------- fused scan (decoupled lookback) + device barrier + scatter ----------------
// 98 CTAs x 1024 threads, all resident -> safe spin barrier.
__global__ void scan_scatter_kernel(const int* __restrict__ inst) {
    __shared__ int s[1024];
    __shared__ int exc_s;
    int t = threadIdx.x, b = blockIdx.x;
    int i = b * 1024 + t;
    int v = (i < TOT_N) ? g_counts[i] : 0;
    if (i < TOT_N) g_counts[i] = 0;
    s[t] = v;
    __syncthreads();
    for (int off = 1; off < 1024; off <<= 1) {
        int x = (t >= off) ? s[t - off] : 0;
        __syncthreads();
        s[t] += x;
        __syncthreads();
    }
    int incl = s[t];
    int total = s[1023];
    if (t == 0) {
        *((volatile unsigned long long*)&g_desc[b]) = (1ull << 32) | (unsigned)total;
        int run = 0;
        for (int p = b - 1; p >= 0; p--) {
            unsigned long long d;
            do { d = *((volatile unsigned long long*)&g_desc[p]); } while ((d >> 32) == 0ull);
            run += (int)(unsigned)d;
            if ((d >> 32) == 2ull) break;
        }
        *((volatile unsigned long long*)&g_desc[b]) = (2ull << 32) | (unsigned)(run + total);
        exc_s = run;
    }
    __syncthreads();
    int e = exc_s;
    if (i < TOT_N) {
        int o = e + incl - v;
        g_offsets[i] = o;
        g_cursor[i] = o;
    }
    if (t == 0 && b == SCAN_BLOCKS - 1) g_offsets[TOT_N] = e + total;

    // ---- device barrier (all 98 CTAs resident) ----
    __syncthreads();
    if (t == 0) {
        __threadfence();
        atomicAdd(&g_bar2, 1u);
        while (*((volatile unsigned int*)&g_bar2) < (unsigned)SCAN_BLOCKS) {}
    }
    __syncthreads();
    __threadfence();

    // ---- scatter phase: grid-stride over all edges ----
    for (int idx = b * 1024 + t; idx < TOT_E; idx += SCAN_BLOCKS * 1024) {
        int m = idx >= EE;
        int eidx = idx - m * EE;
        const int* ip = inst + (size_t)m * EE * 3 + (size_t)eidx * 3;
        int i0 = ip[0], i1 = ip[1], i2 = ip[2];
        int pos = atomicAdd(&g_cursor[m * NN + i0], 1);
        g_einst[pos] = make_int2(i1, i2);
    }
}

// FUSED node kernel: one warp per NODE, both paths (m=0,1) sequential.
// 6 CTAs/SM target (reg budget 42): d0 reloaded per-m so it isn't live across
// the edge loop. All shfl ops run in full-warp-converged regions.
__global__ __launch_bounds__(256, 6) void node_fused_kernel(
    const float* __restrict__ feat, const float* __restrict__ attn2) {
    __shared__ float s_at2[256];
    if (threadIdx.x < 256) s_at2[threadIdx.x] = attn2[threadIdx.x];
    __syncthreads();

    int n = (blockIdx.x * blockDim.x + threadIdx.x) >> 5;
    int lane = threadIdx.x & 31;
    if (n >= NN) return;
    int sub = lane >> 4;
    int li = lane & 15;
    int tig = li & 3;

    const float4* g_fr4 = reinterpret_cast<const float4*>(g_fr);
    float a1own = g_a1n[n * 4 + tig];

#pragma unroll 1
    for (int m = 0; m < 2; m++) {
        int seg = m * NN + n;
        int start = g_offsets[seg];
        int deg = g_offsets[seg + 1] - start;

        float4 f1 = g_fr4[(m * 3 + 1) * 16 + li];
        float c_re0, c_im0, c_re1, c_im1;
        {   // n0 (p=0) contribution: reload d0 each m (keeps it out of loop liveness)
            float4 f0 = g_fr4[(m * 3 + 0) * 16 + li];
            float4 d0 = *reinterpret_cast<const float4*>(feat + (size_t)n * 64 + 4 * li);
            c_re0 = d0.x * f0.x - d0.y * f0.y;
            c_im0 = d0.x * f0.y + d0.y * f0.x;
            c_re1 = d0.z * f0.z - d0.w * f0.w;
            c_im1 = d0.z * f0.w + d0.w * f0.z;
        }

        float acc[4][4];
        float den_own = 0.f;
#pragma unroll
        for (int h = 0; h < 4; h++)
#pragma unroll
            for (int j = 0; j < 4; j++) acc[h][j] = 0.f;

        int padded = (deg + 1) & ~1;
        int2 nd = (sub < padded) ? g_einst[start + ((sub < deg) ? sub : 0)] : make_int2(0, 0);
        for (int i = sub; i < padded; i += 2) {
            bool act = i < deg;
            int2 cur = nd;
            int inext = i + 2;
            if (inext < padded)
                nd = g_einst[start + ((inext < deg) ? inext : 0)];
            float mre0 = c_re0, mim0 = c_im0, mre1 = c_re1, mim1 = c_im1;
            {   // p=1 node: rotate by f1
                float4 d = *reinterpret_cast<const float4*>(feat + (size_t)cur.x * 64 + 4 * li);
                mre0 += d.x * f1.x - d.y * f1.y;
                mim0 += d.x * f1.y + d.y * f1.x;
                mre1 += d.z * f1.z - d.w * f1.w;
                mim1 += d.z * f1.w + d.w * f1.z;
            }
            {   // p=2 node: identity rotation
                float4 d = *reinterpret_cast<const float4*>(feat + (size_t)cur.y * 64 + 4 * li);
                mre0 += d.x; mim0 += d.y;
                mre1 += d.z; mim1 += d.w;
            }
            float ef[4];
            ef[0] = gatef(mre0 * (1.f / 3.f));
            ef[1] = gatef(mim0 * (1.f / 3.f));
            ef[2] = gatef(mre1 * (1.f / 3.f));
            ef[3] = gatef(mim1 * (1.f / 3.f));
            float ph[4];
#pragma unroll
            for (int h = 0; h < 4; h++) {
                float4 a2v = *reinterpret_cast<const float4*>(&s_at2[h * 64 + 4 * li]);
                ph[h] = a2v.x * ef[0] + a2v.y * ef[1] + a2v.z * ef[2] + a2v.w * ef[3];
                ph[h] += __shfl_xor_sync(0xffffffffu, ph[h], 1);
                ph[h] += __shfl_xor_sync(0xffffffffu, ph[h], 2);
            }
            float v = (tig == 0) ? ph[0] : (tig == 1) ? ph[1] : (tig == 2) ? ph[2] : ph[3];
            v += __shfl_xor_sync(0xffffffffu, v, 4);
            v += __shfl_xor_sync(0xffffffffu, v, 8);
            float a = celu3f(a1own + v);
            float w = act ? __expf(a) : 0.f;
            den_own += w;
            float wv0 = __shfl_sync(0xffffffffu, w, 0, 4);
            float wv1 = __shfl_sync(0xffffffffu, w, 1, 4);
            float wv2 = __shfl_sync(0xffffffffu, w, 2, 4);
            float wv3 = __shfl_sync(0xffffffffu, w, 3, 4);
#pragma unroll
            for (int j = 0; j < 4; j++) {
                acc[0][j] += wv0 * ef[j];
                acc[1][j] += wv1 * ef[j];
                acc[2][j] += wv2 * ef[j];
                acc[3][j] += wv3 * ef[j];
            }
        }
        // merge the two subgroups (full warp converged)
        den_own += __shfl_xor_sync(0xffffffffu, den_own, 16);
#pragma unroll
        for (int h = 0; h < 4; h++)
#pragma unroll
            for (int j = 0; j < 4; j++)
                acc[h][j] += __shfl_xor_sync(0xffffffffu, acc[h][j], 16);

        // per-head denominators: broadcast while the FULL warp is converged
        float den0 = __shfl_sync(0xffffffffu, den_own, 0, 4);
        float den1 = __shfl_sync(0xffffffffu, den_own, 1, 4);
        float den2 = __shfl_sync(0xffffffffu, den_own, 2, 4);
        float den3 = __shfl_sync(0xffffffffu, den_own, 3, 4);

        if (sub == 0) {
            float den[4] = {den0, den1, den2, den3};
            float* zr = g_z + (size_t)n * 512 + m * 256;
#pragma unroll
            for (int h = 0; h < 4; h++) {
                float inv = (deg > 0) ? __fdividef(1.f, den[h]) : 0.f;
                float z0 = celu3f(acc[h][0] * inv);
                float z1 = celu3f(acc[h][1] * inv);
                float z2 = celu3f(acc[h][2] * inv);
                float z3 = celu3f(acc[h][3] * inv);
                *reinterpret_cast<float4*>(zr + h * 64 + 4 * li) = make_float4(z0, z1, z2, z3);
            }
        }
    }
}

// ---------------- persistent MLP + grid barrier + final blend ----------------
#define P_SSTRIDE 528
#define P_OFF_W2  135168
#define P_OFF_A   202752
#define P_OFF_FB1 219648
#define P_OFF_FB2 220672
#define P_OFF_FW3 221184
#define P_OFF_RED 221696
#define P_SMEM    221824
#define N_TILES   ((ROWS_TOT + 31) / 32)     // 3125

__global__ __launch_bounds__(512, 1) void mlp_persist_kernel(
    const float* __restrict__ fb1, const float* __restrict__ fb2,
    const float* __restrict__ fw3, float* __restrict__ out) {
    extern __shared__ char smem[];
    char* sw1 = smem;
    char* sw2 = smem + P_OFF_W2;
    char* sa  = smem + P_OFF_A;
    float* fb1s = reinterpret_cast<float*>(smem + P_OFF_FB1);
    float* fb2s = reinterpret_cast<float*>(smem + P_OFF_FB2);
    float* fw3s = reinterpret_cast<float*>(smem + P_OFF_FW3);
    float* red  = reinterpret_cast<float*>(smem + P_OFF_RED);

    uint32_t sw1_u = smem_to_u32(smem);
    uint32_t sw2_u = sw1_u + P_OFF_W2;
    uint32_t sa_u  = sw1_u + P_OFF_A;

    int tid = threadIdx.x;
    int wid = tid >> 5;
    int lane = tid & 31;
    int wm = wid >> 3;
    int wn = wid & 7;
    int m_base = wm * 16;
    int g = lane >> 2;
    int tig = lane & 3;

    for (int idx = tid; idx < 8192; idx += 512) {
        int r = idx >> 5, c = idx & 31;
        uint4 v = *reinterpret_cast<const uint4*>(g_fw1b + r * 256 + c * 8);
        *reinterpret_cast<uint4*>(sw1 + r * P_SSTRIDE + c * 16) = v;
    }
    for (int idx = tid; idx < 4096; idx += 512) {
        int r = idx >> 5, c = idx & 31;
        uint4 v = *reinterpret_cast<const uint4*>(g_fw2b + r * 256 + c * 8);
        *reinterpret_cast<uint4*>(sw2 + r * P_SSTRIDE + c * 16) = v;
    }
    for (int i = tid; i < 256; i += 512) fb1s[i] = fb1[i];
    for (int i = tid; i < 128; i += 512) { fb2s[i] = fb2[i]; fw3s[i] = fw3[i]; }

    int r0 = (tid * 2) >> 5,     c0 = (tid * 2) & 31;
    int r1 = (tid * 2 + 1) >> 5, c1 = (tid * 2 + 1) & 31;

    {
        int rowbase = blockIdx.x * 32;
        float4 a0 = make_float4(0, 0, 0, 0), b0 = a0, a1 = a0, b1 = a0;
        if (rowbase + r0 < ROWS_TOT) {
            const float4* zp = reinterpret_cast<const float4*>(g_z + (size_t)(rowbase + r0) * 256 + c0 * 8);
            a0 = zp[0]; b0 = zp[1];
        }
        if (rowbase + r1 < ROWS_TOT) {
            const float4* zp = reinterpret_cast<const float4*>(g_z + (size_t)(rowbase + r1) * 256 + c1 * 8);
            a1 = zp[0]; b1 = zp[1];
        }
        *reinterpret_cast<uint4*>(sa + r0 * P_SSTRIDE + c0 * 16) = pack_bf16x8(a0, b0);
        *reinterpret_cast<uint4*>(sa + r1 * P_SSTRIDE + c1 * 16) = pack_bf16x8(a1, b1);
    }
    __syncthreads();

    int arow  = m_base + (lane & 15);
    int acol8 = ((lane >> 4) & 1) * 8;
    int brow1 = wn * 32 + ((lane >> 4) & 1) * 8 + (lane & 7);
    int brow2 = wn * 16 + ((lane >> 4) & 1) * 8 + (lane & 7);
    int bcol8 = ((lane >> 3) & 1) * 8;

    float ws0 = 0.f, ws1 = 0.f;

    for (int t = blockIdx.x; t < N_TILES; t += MLP_GRID) {
        int rowbase = t * 32;
        int tn = t + MLP_GRID;
        bool has_next = tn < N_TILES;

        float4 pa0 = make_float4(0, 0, 0, 0), pb0 = pa0, pa1 = pa0, pb1 = pa0;
        if (has_next) {
            int nb = tn * 32;
            if (nb + r0 < ROWS_TOT) {
                const float4* zp = reinterpret_cast<const float4*>(g_z + (size_t)(nb + r0) * 256 + c0 * 8);
                pa0 = zp[0]; pb0 = zp[1];
            }
            if (nb + r1 < ROWS_TOT) {
                const float4* zp = reinterpret_cast<const float4*>(g_z + (size_t)(nb + r1) * 256 + c1 * 8);
                pa1 = zp[0]; pb1 = zp[1];
            }
        }

        float acc[4][4];
#pragma unroll
        for (int nt = 0; nt < 4; nt++)
#pragma unroll
            for (int c = 0; c < 4; c++) acc[nt][c] = 0.f;
#pragma unroll
        for (int k = 0; k < 256; k += 16) {
            uint32_t af[4];
            ldsm_x4(sa_u + arow * P_SSTRIDE + (k + acol8) * 2, af);
#pragma unroll
            for (int np = 0; np < 2; np++) {
                uint32_t bf[4];
                ldsm_x4(sw1_u + (brow1 + np * 16) * P_SSTRIDE + (k + bcol8) * 2, bf);
                mma_bf16(acc[np * 2],     af, bf);
                mma_bf16(acc[np * 2 + 1], af, bf + 2);
            }
        }
        __syncthreads();

#pragma unroll
        for (int nt = 0; nt < 4; nt++) {
            int row = m_base + g;
            int col = wn * 32 + nt * 8 + tig * 2;
            float b0 = fb1s[col], b1 = fb1s[col + 1];
            float t0 = celu3f(acc[nt][0] + b0);
            float t1 = celu3f(acc[nt][1] + b1);
            float t2 = celu3f(acc[nt][2] + b0);
            float t3 = celu3f(acc[nt][3] + b1);
            __nv_bfloat162 p01 = __floats2bfloat162_rn(t0, t1);
            __nv_bfloat162 p23 = __floats2bfloat162_rn(t2, t3);
            *reinterpret_cast<uint32_t*>(sa + row * P_SSTRIDE + col * 2) =
                *reinterpret_cast<uint32_t*>(&p01);
            *reinterpret_cast<uint32_t*>(sa + (row + 8) * P_SSTRIDE + col * 2) =
                *reinterpret_cast<uint32_t*>(&p23);
        }
        __syncthreads();

        float acc2[2][4];
#pragma unroll
        for (int nt = 0; nt < 2; nt++)
#pragma unroll
            for (int c = 0; c < 4; c++) acc2[nt][c] = 0.f;
#pragma unroll
        for (int k = 0; k < 256; k += 16) {
            uint32_t af[4];
            ldsm_x4(sa_u + arow * P_SSTRIDE + (k + acol8) * 2, af);
            uint32_t bf[4];
            ldsm_x4(sw2_u + brow2 * P_SSTRIDE + (k + bcol8) * 2, bf);
            mma_bf16(acc2[0], af, bf);
            mma_bf16(acc2[1], af, bf + 2);
        }

        {
            int row0 = rowbase + m_base + g;
            int row1 = row0 + 8;
            float sA = 0.f, sB = 0.f;
#pragma unroll
            for (int nt = 0; nt < 2; nt++) {
                int col = wn * 16 + nt * 8 + tig * 2;
                float b0 = fb2s[col], b1 = fb2s[col + 1];
                float w0 = fw3s[col], w1 = fw3s[col + 1];
                sA += celu3f(acc2[nt][0] + b0) * w0 + celu3f(acc2[nt][1] + b1) * w1;
                sB += celu3f(acc2[nt][2] + b0) * w0 + celu3f(acc2[nt][3] + b1) * w1;
            }
            int p = g & 1;
            float s = 0.f;
            if (row0 < ROWS_TOT) s += sA;
            if (row1 < ROWS_TOT) s += sB;
            if (p) ws1 += s; else ws0 += s;
        }
        __syncthreads();

        if (has_next) {
            *reinterpret_cast<uint4*>(sa + r0 * P_SSTRIDE + c0 * 16) = pack_bf16x8(pa0, pb0);
            *reinterpret_cast<uint4*>(sa + r1 * P_SSTRIDE + c1 * 16) = pack_bf16x8(pa1, pb1);
        }
        __syncthreads();
    }

    ws0 = wredsum(ws0);
    ws1 = wredsum(ws1);
    if (lane == 0) { red[wid * 2] = ws0; red[wid * 2 + 1] = ws1; }
    __syncthreads();
    if (tid == 0) {
        float s0 = 0.f, s1 = 0.f;
#pragma unroll
        for (int w = 0; w < 16; w++) { s0 += red[w * 2]; s1 += red[w * 2 + 1]; }
        atomicAdd(&g_w[0], s0);
        atomicAdd(&g_w[1], s1);
    }

    // ---- grid barrier (all 148 CTAs resident at 1 CTA/SM) ----
    __syncthreads();
    if (tid == 0) {
        __threadfence();
        atomicAdd(&g_bar, 1u);
        while (*((volatile unsigned int*)&g_bar) < (unsigned)MLP_GRID) {}
    }
    __syncthreads();
    __threadfence();

    // ---- beta + final blend ----
    float w0 = *((volatile float*)&g_w[0]) * (1.f / (float)NN);
    float w1 = *((volatile float*)&g_w[1]) * (1.f / (float)NN);
    float mx = fmaxf(w0, w1);
    float e0 = expf(w0 - mx), e1 = expf(w1 - mx);
    float binv = 1.f / (e0 + e1);
    float beta0 = e0 * binv, beta1 = e1 * binv;

    for (int idx = blockIdx.x * 512 + tid; idx < NN * 64; idx += MLP_GRID * 512) {
        int n = idx >> 6;
        int q = idx & 63;
        float4 z0 = reinterpret_cast<const float4*>(g_z)[(size_t)n * 128 + q];
        float4 z1 = reinterpret_cast<const float4*>(g_z)[(size_t)n * 128 + 64 + q];
        float4 o;
        o.x = beta0 * z0.x + beta1 * z1.x;
        o.y = beta0 * z0.y + beta1 * z1.y;
        o.z = beta0 * z0.z + beta1 * z1.z;
        o.w = beta0 * z0.w + beta1 * z1.w;
        reinterpret_cast<float4*>(out)[idx] = o;
    }
}

// ---------------- launch ----------------
extern "C" void kernel_launch(void* const* d_in, const int* in_sizes, int n_in,
                              void* d_out, int out_size) {
    const float* feat    = (const float*)d_in[0];
    const float* r_vec   = (const float*)d_in[1];
    const float* attn1_w = (const float*)d_in[2];
    const float* attn2   = (const float*)d_in[3];
    const float* fw1     = (const float*)d_in[4];
    const float* fb1     = (const float*)d_in[5];
    const float* fw2     = (const float*)d_in[6];
    const float* fb2     = (const float*)d_in[7];
    const float* fw3     = (const float*)d_in[8];
    const int*   inst    = (const int*)d_in[9];
    float* out = (float*)d_out;

    prep_kernel<<<PREP_GRID, 256>>>(feat, r_vec, attn1_w, fw1, fw2, inst);
    scan_scatter_kernel<<<SCAN_BLOCKS, 1024>>>(inst);
    node_fused_kernel<<<(NN * 32 + 255) / 256, 256>>>(feat, attn2);

    cudaFuncSetAttribute(mlp_persist_kernel, cudaFuncAttributeMaxDynamicSharedMemorySize, P_SMEM);
    mlp_persist_kernel<<<MLP_GRID, 512, P_SMEM>>>(fb1, fb2, fw3, out);
}

// round 17
// speedup vs baseline: 1.2764x; 1.0184x over previous
#include <cuda_runtime.h>
#include <cuda_bf16.h>
#include <math.h>
#include <float.h>
#include <stdint.h>

// Problem constants (fixed by dataset)
#define NN 50000
#define HH 64
#define EE 250000
#define HEADS 4
#define TOT_E (2 * EE)             // edges across both paths
#define TOT_N (2 * NN)             // segments across both paths
#define ROWS_TOT (NN * 2)          // 100000 MLP rows (N nodes x 2 paths)
#define SCAN_BLOCKS ((TOT_N + 1023) / 1024)   // 98
#define MLP_GRID  148

// ---------------- scratch (static device memory; no allocs) ----------------
__device__ float g_fr[2][3][32][2];
__device__ float g_a1n[NN * 4];
__device__ int   g_counts[TOT_N];          // re-zeroed by scan each run
__device__ int   g_offsets[TOT_N + 1];
__device__ int   g_cursor[TOT_N];
__device__ unsigned long long g_desc[SCAN_BLOCKS];
__device__ unsigned int g_bar;             // MLP grid barrier
__device__ unsigned int g_bar2;            // scan/scatter grid barrier
__device__ __align__(8) int2 g_einst[TOT_E];  // CSR-sorted (n1,n2) per edge
__device__ float g_z[(size_t)NN * 512];       // fp32 rows: row (2n+m) x 256
__device__ __align__(16) __nv_bfloat16 g_fw1b[256 * 256];
__device__ __align__(16) __nv_bfloat16 g_fw2b[128 * 256];
__device__ float g_w[2];

// ---------------- helpers ----------------
__device__ __forceinline__ float celu3f(float x) {
    return x > 0.f ? x : 3.f * (__expf(x * (1.f / 3.f)) - 1.f);
}
__device__ __forceinline__ float gatef(float x) {
    float e1 = __expf(x * (1.f / 3.f));
    float e3 = e1 * e1 * e1;                    // exp(x)
    float s  = __fdividef(e3, e3 + 1.f);        // sigmoid(x)
    float c1 = x > 0.f ? x : 3.f * (e1 - 1.f);  // celu3(x)
    float se = c1 * s;
    return se > 0.f ? se : 3.f * (__expf(se * (1.f / 3.f)) - 1.f);
}
__device__ __forceinline__ float wredsum(float v) {
#pragma unroll
    for (int o = 16; o; o >>= 1) v += __shfl_xor_sync(0xffffffffu, v, o);
    return v;
}
__device__ __forceinline__ uint32_t smem_to_u32(const void* p) {
    uint32_t a;
    asm("{ .reg .u64 t; cvta.to.shared.u64 t, %1; cvt.u32.u64 %0, t; }" : "=r"(a) : "l"(p));
    return a;
}
__device__ __forceinline__ void ldsm_x4(uint32_t addr, uint32_t* r) {
    asm volatile("ldmatrix.sync.aligned.m8n8.x4.shared.b16 {%0,%1,%2,%3}, [%4];"
                 : "=r"(r[0]), "=r"(r[1]), "=r"(r[2]), "=r"(r[3]) : "r"(addr));
}
__device__ __forceinline__ void ldsm_x2(uint32_t addr, uint32_t* r) {
    asm volatile("ldmatrix.sync.aligned.m8n8.x2.shared.b16 {%0,%1}, [%2];"
                 : "=r"(r[0]), "=r"(r[1]) : "r"(addr));
}
__device__ __forceinline__ void mma_bf16(float* d, const uint32_t* a, const uint32_t* b) {
    asm volatile(
        "mma.sync.aligned.m16n8k16.row.col.f32.bf16.bf16.f32 "
        "{%0,%1,%2,%3}, {%4,%5,%6,%7}, {%8,%9}, {%0,%1,%2,%3};"
        : "+f"(d[0]), "+f"(d[1]), "+f"(d[2]), "+f"(d[3])
        : "r"(a[0]), "r"(a[1]), "r"(a[2]), "r"(a[3]), "r"(b[0]), "r"(b[1]));
}
__device__ __forceinline__ uint4 pack_bf16x8(float4 a, float4 b) {
    __nv_bfloat162 h0 = __floats2bfloat162_rn(a.x, a.y);
    __nv_bfloat162 h1 = __floats2bfloat162_rn(a.z, a.w);
    __nv_bfloat162 h2 = __floats2bfloat162_rn(b.x, b.y);
    __nv_bfloat162 h3 = __floats2bfloat162_rn(b.z, b.w);
    uint4 u;
    u.x = *reinterpret_cast<uint32_t*>(&h0);
    u.y = *reinterpret_cast<uint32_t*>(&h1);
    u.z = *reinterpret_cast<uint32_t*>(&h2);
    u.w = *reinterpret_cast<uint32_t*>(&h3);
    return u;
}

// ---------------- fused prep kernel (init + wconv + a1n + count) ----------------
#define PREP_WCONV_B 1
#define PREP_A1N_B   257
#define PREP_CNT_B   6507
#define PREP_GRID    8461

__global__ void prep_kernel(const float* __restrict__ feat, const float* __restrict__ r_vec,
                            const float* __restrict__ aw,
                            const float* __restrict__ fw1, const float* __restrict__ fw2,
                            const int* __restrict__ inst) {
    int b = blockIdx.x;
    int tid = threadIdx.x;
    if (b == 0) {
        if (tid < 2) g_w[tid] = 0.f;
        if (tid == 0) { g_bar = 0u; g_bar2 = 0u; }
        if (tid < SCAN_BLOCKS) g_desc[tid] = 0ull;
        if (tid < 32) {
            int t = tid;
            float nre[4], nim[4];
#pragma unroll
            for (int r = 0; r < 4; r++) {
                float re = r_vec[r * 64 + t * 2];
                float im = r_vec[r * 64 + t * 2 + 1];
                float inv = rsqrtf(re * re + im * im);
                nre[r] = re * inv;
                nim[r] = im * inv;
            }
#pragma unroll
            for (int m = 0; m < 2; m++) {
                int a = 2 * m + 1, c = 2 * m;
                g_fr[m][2][t][0] = 1.f; g_fr[m][2][t][1] = 0.f;
                g_fr[m][1][t][0] = nre[a]; g_fr[m][1][t][1] = nim[a];
                g_fr[m][0][t][0] = nre[a] * nre[c] - nim[a] * nim[c];
                g_fr[m][0][t][1] = nre[a] * nim[c] + nim[a] * nre[c];
            }
        }
    } else if (b < PREP_A1N_B) {
        int i = (b - PREP_WCONV_B) * 256 + tid;
        if (i < 256 * 256) g_fw1b[i] = __float2bfloat16(fw1[i]);
        if (i < 128 * 256) g_fw2b[i] = __float2bfloat16(fw2[i]);
    } else if (b < PREP_CNT_B) {
        int gw = (b - PREP_A1N_B) * 8 + (tid >> 5);
        int lane = tid & 31;
        if (gw < NN) {
            float2 d = reinterpret_cast<const float2*>(feat)[gw * 32 + lane];
            float p[4];
#pragma unroll
            for (int h = 0; h < 4; h++) {
                float v = aw[h * 64 + 2 * lane] * d.x + aw[h * 64 + 2 * lane + 1] * d.y;
                p[h] = wredsum(v);
            }
            if (lane == 0) {
                float4 r;
                r.x = celu3f(p[0]); r.y = celu3f(p[1]); r.z = celu3f(p[2]); r.w = celu3f(p[3]);
                reinterpret_cast<float4*>(g_a1n)[gw] = r;
            }
        }
    } else {
        int idx = (b - PREP_CNT_B) * 256 + tid;
        if (idx < TOT_E) {
            int m = idx >= EE;
            int e = idx - m * EE;
            int seg = inst[(size_t)m * EE * 3 + (size_t)e * 3];
            atomicAdd(&g_counts[m * NN + seg], 1);
        }
    }
}

// ---------------- fused scan (decoupled lookback) + device barrier + scatter ----------------
__global__ void scan_scatter_kernel(const int* __restrict__ inst) {
    __shared__ int s[1024];
    __shared__ int exc_s;
    int t = threadIdx.x, b = blockIdx.x;
    int i = b * 1024 + t;
    int v = (i < TOT_N) ? g_counts[i] : 0;
    if (i < TOT_N) g_counts[i] = 0;
    s[t] = v;
    __syncthreads();
    for (int off = 1; off < 1024; off <<= 1) {
        int x = (t >= off) ? s[t - off] : 0;
        __syncthreads();
        s[t] += x;
        __syncthreads();
    }
    int incl = s[t];
    int total = s[1023];
    if (t == 0) {
        *((volatile unsigned long long*)&g_desc[b]) = (1ull << 32) | (unsigned)total;
        int run = 0;
        for (int p = b - 1; p >= 0; p--) {
            unsigned long long d;
            do { d = *((volatile unsigned long long*)&g_desc[p]); } while ((d >> 32) == 0ull);
            run += (int)(unsigned)d;
            if ((d >> 32) == 2ull) break;
        }
        *((volatile unsigned long long*)&g_desc[b]) = (2ull << 32) | (unsigned)(run + total);
        exc_s = run;
    }
    __syncthreads();
    int e = exc_s;
    if (i < TOT_N) {
        int o = e + incl - v;
        g_offsets[i] = o;
        g_cursor[i] = o;
    }
    if (t == 0 && b == SCAN_BLOCKS - 1) g_offsets[TOT_N] = e + total;

    // ---- device barrier (all 98 CTAs resident) ----
    __syncthreads();
    if (t == 0) {
        __threadfence();
        atomicAdd(&g_bar2, 1u);
        while (*((volatile unsigned int*)&g_bar2) < (unsigned)SCAN_BLOCKS) {}
    }
    __syncthreads();
    __threadfence();

    // ---- scatter phase: grid-stride over all edges ----
    for (int idx = b * 1024 + t; idx < TOT_E; idx += SCAN_BLOCKS * 1024) {
        int m = idx >= EE;
        int eidx = idx - m * EE;
        const int* ip = inst + (size_t)m * EE * 3 + (size_t)eidx * 3;
        int i0 = ip[0], i1 = ip[1], i2 = ip[2];
        int pos = atomicAdd(&g_cursor[m * NN + i0], 1);
        g_einst[pos] = make_int2(i1, i2);
    }
}

// FUSED node kernel: one warp per NODE, both paths (m=0,1) sequential.
__global__ __launch_bounds__(256, 6) void node_fused_kernel(
    const float* __restrict__ feat, const float* __restrict__ attn2) {
    __shared__ float s_at2[256];
    if (threadIdx.x < 256) s_at2[threadIdx.x] = attn2[threadIdx.x];
    __syncthreads();

    int n = (blockIdx.x * blockDim.x + threadIdx.x) >> 5;
    int lane = threadIdx.x & 31;
    if (n >= NN) return;
    int sub = lane >> 4;
    int li = lane & 15;
    int tig = li & 3;

    const float4* g_fr4 = reinterpret_cast<const float4*>(g_fr);
    float a1own = g_a1n[n * 4 + tig];

#pragma unroll 1
    for (int m = 0; m < 2; m++) {
        int seg = m * NN + n;
        int start = g_offsets[seg];
        int deg = g_offsets[seg + 1] - start;

        float4 f1 = g_fr4[(m * 3 + 1) * 16 + li];
        float c_re0, c_im0, c_re1, c_im1;
        {
            float4 f0 = g_fr4[(m * 3 + 0) * 16 + li];
            float4 d0 = *reinterpret_cast<const float4*>(feat + (size_t)n * 64 + 4 * li);
            c_re0 = d0.x * f0.x - d0.y * f0.y;
            c_im0 = d0.x * f0.y + d0.y * f0.x;
            c_re1 = d0.z * f0.z - d0.w * f0.w;
            c_im1 = d0.z * f0.w + d0.w * f0.z;
        }

        float acc[4][4];
        float den_own = 0.f;
#pragma unroll
        for (int h = 0; h < 4; h++)
#pragma unroll
            for (int j = 0; j < 4; j++) acc[h][j] = 0.f;

        int padded = (deg + 1) & ~1;
        int2 nd = (sub < padded) ? g_einst[start + ((sub < deg) ? sub : 0)] : make_int2(0, 0);
        for (int i = sub; i < padded; i += 2) {
            bool act = i < deg;
            int2 cur = nd;
            int inext = i + 2;
            if (inext < padded)
                nd = g_einst[start + ((inext < deg) ? inext : 0)];
            float mre0 = c_re0, mim0 = c_im0, mre1 = c_re1, mim1 = c_im1;
            {
                float4 d = *reinterpret_cast<const float4*>(feat + (size_t)cur.x * 64 + 4 * li);
                mre0 += d.x * f1.x - d.y * f1.y;
                mim0 += d.x * f1.y + d.y * f1.x;
                mre1 += d.z * f1.z - d.w * f1.w;
                mim1 += d.z * f1.w + d.w * f1.z;
            }
            {
                float4 d = *reinterpret_cast<const float4*>(feat + (size_t)cur.y * 64 + 4 * li);
                mre0 += d.x; mim0 += d.y;
                mre1 += d.z; mim1 += d.w;
            }
            float ef[4];
            ef[0] = gatef(mre0 * (1.f / 3.f));
            ef[1] = gatef(mim0 * (1.f / 3.f));
            ef[2] = gatef(mre1 * (1.f / 3.f));
            ef[3] = gatef(mim1 * (1.f / 3.f));
            float ph[4];
#pragma unroll
            for (int h = 0; h < 4; h++) {
                float4 a2v = *reinterpret_cast<const float4*>(&s_at2[h * 64 + 4 * li]);
                ph[h] = a2v.x * ef[0] + a2v.y * ef[1] + a2v.z * ef[2] + a2v.w * ef[3];
                ph[h] += __shfl_xor_sync(0xffffffffu, ph[h], 1);
                ph[h] += __shfl_xor_sync(0xffffffffu, ph[h], 2);
            }
            float v = (tig == 0) ? ph[0] : (tig == 1) ? ph[1] : (tig == 2) ? ph[2] : ph[3];
            v += __shfl_xor_sync(0xffffffffu, v, 4);
            v += __shfl_xor_sync(0xffffffffu, v, 8);
            float a = celu3f(a1own + v);
            float w = act ? __expf(a) : 0.f;
            den_own += w;
            float wv0 = __shfl_sync(0xffffffffu, w, 0, 4);
            float wv1 = __shfl_sync(0xffffffffu, w, 1, 4);
            float wv2 = __shfl_sync(0xffffffffu, w, 2, 4);
            float wv3 = __shfl_sync(0xffffffffu, w, 3, 4);
#pragma unroll
            for (int j = 0; j < 4; j++) {
                acc[0][j] += wv0 * ef[j];
                acc[1][j] += wv1 * ef[j];
                acc[2][j] += wv2 * ef[j];
                acc[3][j] += wv3 * ef[j];
            }
        }
        den_own += __shfl_xor_sync(0xffffffffu, den_own, 16);
#pragma unroll
        for (int h = 0; h < 4; h++)
#pragma unroll
            for (int j = 0; j < 4; j++)
                acc[h][j] += __shfl_xor_sync(0xffffffffu, acc[h][j], 16);

        float den0 = __shfl_sync(0xffffffffu, den_own, 0, 4);
        float den1 = __shfl_sync(0xffffffffu, den_own, 1, 4);
        float den2 = __shfl_sync(0xffffffffu, den_own, 2, 4);
        float den3 = __shfl_sync(0xffffffffu, den_own, 3, 4);

        if (sub == 0) {
            float den[4] = {den0, den1, den2, den3};
            float* zr = g_z + (size_t)n * 512 + m * 256;
#pragma unroll
            for (int h = 0; h < 4; h++) {
                float inv = (deg > 0) ? __fdividef(1.f, den[h]) : 0.f;
                float z0 = celu3f(acc[h][0] * inv);
                float z1 = celu3f(acc[h][1] * inv);
                float z2 = celu3f(acc[h][2] * inv);
                float z3 = celu3f(acc[h][3] * inv);
                *reinterpret_cast<float4*>(zr + h * 64 + 4 * li) = make_float4(z0, z1, z2, z3);
            }
        }
    }
}

// ---------------- persistent MLP (1024 threads) + grid barrier + final blend ----------------
// 32 warps: layer1 warp tile 16x16 (wm=wid>>4, wn=wid&15), layer2 warp tile 16x8.
#define P_SSTRIDE 528
#define P_OFF_W2  135168
#define P_OFF_A   202752
#define P_OFF_FB1 219648
#define P_OFF_FB2 220672
#define P_OFF_FW3 221184
#define P_OFF_RED 221696
#define P_SMEM    221984
#define N_TILES   ((ROWS_TOT + 31) / 32)     // 3125

__global__ __launch_bounds__(1024, 1) void mlp_persist_kernel(
    const float* __restrict__ fb1, const float* __restrict__ fb2,
    const float* __restrict__ fw3, float* __restrict__ out) {
    extern __shared__ char smem[];
    char* sw1 = smem;
    char* sw2 = smem + P_OFF_W2;
    char* sa  = smem + P_OFF_A;
    float* fb1s = reinterpret_cast<float*>(smem + P_OFF_FB1);
    float* fb2s = reinterpret_cast<float*>(smem + P_OFF_FB2);
    float* fw3s = reinterpret_cast<float*>(smem + P_OFF_FW3);
    float* red  = reinterpret_cast<float*>(smem + P_OFF_RED);   // 64 floats

    uint32_t sw1_u = smem_to_u32(smem);
    uint32_t sw2_u = sw1_u + P_OFF_W2;
    uint32_t sa_u  = sw1_u + P_OFF_A;

    int tid = threadIdx.x;
    int wid = tid >> 5;
    int lane = tid & 31;
    int wm = wid >> 4;        // 0/1 -> 16-row half
    int wn = wid & 15;        // 0..15
    int m_base = wm * 16;
    int g = lane >> 2;
    int tig = lane & 3;

    for (int idx = tid; idx < 8192; idx += 1024) {
        int r = idx >> 5, c = idx & 31;
        uint4 v = *reinterpret_cast<const uint4*>(g_fw1b + r * 256 + c * 8);
        *reinterpret_cast<uint4*>(sw1 + r * P_SSTRIDE + c * 16) = v;
    }
    for (int idx = tid; idx < 4096; idx += 1024) {
        int r = idx >> 5, c = idx & 31;
        uint4 v = *reinterpret_cast<const uint4*>(g_fw2b + r * 256 + c * 8);
        *reinterpret_cast<uint4*>(sw2 + r * P_SSTRIDE + c * 16) = v;
    }
    for (int i = tid; i < 256; i += 1024) fb1s[i] = fb1[i];
    for (int i = tid; i < 128; i += 1024) { fb2s[i] = fb2[i]; fw3s[i] = fw3[i]; }

    // A chunk ownership: thread owns chunk tid (16B bf16 = 8 fp32)
    int ar = tid >> 5, ac = tid & 31;

    {
        int rowbase = blockIdx.x * 32;
        float4 a0 = make_float4(0, 0, 0, 0), b0 = a0;
        if (rowbase + ar < ROWS_TOT) {
            const float4* zp = reinterpret_cast<const float4*>(g_z + (size_t)(rowbase + ar) * 256 + ac * 8);
            a0 = zp[0]; b0 = zp[1];
        }
        *reinterpret_cast<uint4*>(sa + ar * P_SSTRIDE + ac * 16) = pack_bf16x8(a0, b0);
    }
    __syncthreads();

    int arow   = m_base + (lane & 15);
    int acol8  = ((lane >> 4) & 1) * 8;
    int brow1  = wn * 16 + ((lane >> 4) & 1) * 8 + (lane & 7);
    int bcol8  = ((lane >> 3) & 1) * 8;
    int brow2  = wn * 8 + (lane & 7);
    int bcol8b = ((lane >> 3) & 1) * 8;

    float ws0 = 0.f, ws1 = 0.f;

    for (int t = blockIdx.x; t < N_TILES; t += MLP_GRID) {
        int rowbase = t * 32;
        int tn = t + MLP_GRID;
        bool has_next = tn < N_TILES;

        float4 pa0 = make_float4(0, 0, 0, 0), pb0 = pa0;
        if (has_next) {
            int nb = tn * 32;
            if (nb + ar < ROWS_TOT) {
                const float4* zp = reinterpret_cast<const float4*>(g_z + (size_t)(nb + ar) * 256 + ac * 8);
                pa0 = zp[0]; pb0 = zp[1];
            }
        }

        // layer 1: C[32x256] = A @ W1^T ; warp tile 16x16
        float acc[2][4];
#pragma unroll
        for (int nt = 0; nt < 2; nt++)
#pragma unroll
            for (int c = 0; c < 4; c++) acc[nt][c] = 0.f;
#pragma unroll
        for (int k = 0; k < 256; k += 16) {
            uint32_t af[4];
            ldsm_x4(sa_u + arow * P_SSTRIDE + (k + acol8) * 2, af);
            uint32_t bf[4];
            ldsm_x4(sw1_u + brow1 * P_SSTRIDE + (k + bcol8) * 2, bf);
            mma_bf16(acc[0], af, bf);
            mma_bf16(acc[1], af, bf + 2);
        }
        __syncthreads();

        // epilogue 1: t1 = celu3(C + fb1) -> bf16 back into A region
#pragma unroll
        for (int nt = 0; nt < 2; nt++) {
            int row = m_base + g;
            int col = wn * 16 + nt * 8 + tig * 2;
            float b0 = fb1s[col], b1 = fb1s[col + 1];
            float t0 = celu3f(acc[nt][0] + b0);
            float t1 = celu3f(acc[nt][1] + b1);
            float t2 = celu3f(acc[nt][2] + b0);
            float t3 = celu3f(acc[nt][3] + b1);
            __nv_bfloat162 p01 = __floats2bfloat162_rn(t0, t1);
            __nv_bfloat162 p23 = __floats2bfloat162_rn(t2, t3);
            *reinterpret_cast<uint32_t*>(sa + row * P_SSTRIDE + col * 2) =
                *reinterpret_cast<uint32_t*>(&p01);
            *reinterpret_cast<uint32_t*>(sa + (row + 8) * P_SSTRIDE + col * 2) =
                *reinterpret_cast<uint32_t*>(&p23);
        }
        __syncthreads();

        // layer 2: C2[32x128] = t1 @ W2^T ; warp tile 16x8
        float acc2[4];
#pragma unroll
        for (int c = 0; c < 4; c++) acc2[c] = 0.f;
#pragma unroll
        for (int k = 0; k < 256; k += 16) {
            uint32_t af[4];
            ldsm_x4(sa_u + arow * P_SSTRIDE + (k + acol8) * 2, af);
            uint32_t bf[2];
            ldsm_x2(sw2_u + brow2 * P_SSTRIDE + (k + bcol8b) * 2, bf);
            mma_bf16(acc2, af, bf);
        }

        // epilogue 2: per-row w contribution, split by path parity (row&1)
        {
            int row0 = rowbase + m_base + g;
            int row1 = row0 + 8;
            int col = wn * 8 + tig * 2;
            float b0 = fb2s[col], b1 = fb2s[col + 1];
            float w0 = fw3s[col], w1 = fw3s[col + 1];
            float sA = celu3f(acc2[0] + b0) * w0 + celu3f(acc2[1] + b1) * w1;
            float sB = celu3f(acc2[2] + b0) * w0 + celu3f(acc2[3] + b1) * w1;
            int p = g & 1;
            float s = 0.f;
            if (row0 < ROWS_TOT) s += sA;
            if (row1 < ROWS_TOT) s += sB;
            if (p) ws1 += s; else ws0 += s;
        }
        __syncthreads();

        if (has_next) {
            *reinterpret_cast<uint4*>(sa + ar * P_SSTRIDE + ac * 16) = pack_bf16x8(pa0, pb0);
        }
        __syncthreads();
    }

    ws0 = wredsum(ws0);
    ws1 = wredsum(ws1);
    if (lane == 0) { red[wid * 2] = ws0; red[wid * 2 + 1] = ws1; }
    __syncthreads();
    if (tid == 0) {
        float s0 = 0.f, s1 = 0.f;
#pragma unroll
        for (int w = 0; w < 32; w++) { s0 += red[w * 2]; s1 += red[w * 2 + 1]; }
        atomicAdd(&g_w[0], s0);
        atomicAdd(&g_w[1], s1);
    }

    // ---- grid barrier (all 148 CTAs resident at 1 CTA/SM) ----
    __syncthreads();
    if (tid == 0) {
        __threadfence();
        atomicAdd(&g_bar, 1u);
        while (*((volatile unsigned int*)&g_bar) < (unsigned)MLP_GRID) {}
    }
    __syncthreads();
    __threadfence();

    // ---- beta + final blend ----
    float w0 = *((volatile float*)&g_w[0]) * (1.f / (float)NN);
    float w1 = *((volatile float*)&g_w[1]) * (1.f / (float)NN);
    float mx = fmaxf(w0, w1);
    float e0 = expf(w0 - mx), e1 = expf(w1 - mx);
    float binv = 1.f / (e0 + e1);
    float beta0 = e0 * binv, beta1 = e1 * binv;

    for (int idx = blockIdx.x * 1024 + tid; idx < NN * 64; idx += MLP_GRID * 1024) {
        int n = idx >> 6;
        int q = idx & 63;
        float4 z0 = reinterpret_cast<const float4*>(g_z)[(size_t)n * 128 + q];
        float4 z1 = reinterpret_cast<const float4*>(g_z)[(size_t)n * 128 + 64 + q];
        float4 o;
        o.x = beta0 * z0.x + beta1 * z1.x;
        o.y = beta0 * z0.y + beta1 * z1.y;
        o.z = beta0 * z0.z + beta1 * z1.z;
        o.w = beta0 * z0.w + beta1 * z1.w;
        reinterpret_cast<float4*>(out)[idx] = o;
    }
}

// ---------------- launch ----------------
extern "C" void kernel_launch(void* const* d_in, const int* in_sizes, int n_in,
                              void* d_out, int out_size) {
    const float* feat    = (const float*)d_in[0];
    const float* r_vec   = (const float*)d_in[1];
    const float* attn1_w = (const float*)d_in[2];
    const float* attn2   = (const float*)d_in[3];
    const float* fw1     = (const float*)d_in[4];
    const float* fb1     = (const float*)d_in[5];
    const float* fw2     = (const float*)d_in[6];
    const float* fb2     = (const float*)d_in[7];
    const float* fw3     = (const float*)d_in[8];
    const int*   inst    = (const int*)d_in[9];
    float* out = (float*)d_out;

    prep_kernel<<<PREP_GRID, 256>>>(feat, r_vec, attn1_w, fw1, fw2, inst);
    scan_scatter_kernel<<<SCAN_BLOCKS, 1024>>>(inst);
    node_fused_kernel<<<(NN * 32 + 255) / 256, 256>>>(feat, attn2);

    cudaFuncSetAttribute(mlp_persist_kernel, cudaFuncAttributeMaxDynamicSharedMemorySize, P_SMEM);
    mlp_persist_kernel<<<MLP_GRID, 1024, P_SMEM>>>(fb1, fb2, fw3, out);
}